// round 1
// baseline (speedup 1.0000x reference)
#include <cuda_runtime.h>

#define HH 128
#define WW 128
#define HWP (HH*WW)
#define CC 64
#define OO 64
#define BB 4
#define NCH 18   // 2*K*K offset channels

// scratch for offset conv output [B,18,H,W]
__device__ float g_offset[BB*NCH*HH*WW];

// ---------------------------------------------------------------------------
// Kernel 1: offset = conv3x3(x, offset_w) + offset_b
// grid = B*H blocks (one output row each), 128 threads (one pixel each).
// 18 accumulators per thread; weights staged in smem with ch-padded rows so
// the inner product is 18 FFMA per 4xLDS.128 + LDS.64 (broadcast, no conflicts)
// ---------------------------------------------------------------------------
__global__ __launch_bounds__(128) void offset_conv_kernel(
    const float* __restrict__ x,
    const float* __restrict__ ow,   // [18,64,3,3]
    const float* __restrict__ ob)   // [18]
{
    __shared__ float ws[576*20];    // [c*9+t][ch padded to 20]
    __shared__ float bs[NCH];
    int tid = threadIdx.x;

    for (int i = tid; i < 576*18; i += 128) {
        int ct = i / 18, ch = i - ct*18;
        ws[ct*20 + ch] = ow[ch*576 + ct];
    }
    if (tid < NCH) bs[tid] = ob[tid];
    __syncthreads();

    int b  = blockIdx.x >> 7;
    int ho = blockIdx.x & 127;
    int wo = tid;

    float acc[18];
    #pragma unroll
    for (int i = 0; i < 18; ++i) acc[i] = bs[i];

    const float* xb = x + (size_t)b*CC*HWP;

    for (int c = 0; c < CC; ++c) {
        const float* xc = xb + c*HWP;
        float xv[9];
        #pragma unroll
        for (int dy = 0; dy < 3; ++dy) {
            int y = ho - 1 + dy;
            bool vy = ((unsigned)y < (unsigned)HH);
            #pragma unroll
            for (int dx = 0; dx < 3; ++dx) {
                int xx = wo - 1 + dx;
                bool v = vy && ((unsigned)xx < (unsigned)WW);
                xv[dy*3+dx] = v ? xc[y*WW + xx] : 0.f;
            }
        }
        #pragma unroll
        for (int t = 0; t < 9; ++t) {
            const float* wr = ws + (c*9+t)*20;
            float4 w0 = *(const float4*)(wr);
            float4 w1 = *(const float4*)(wr+4);
            float4 w2 = *(const float4*)(wr+8);
            float4 w3 = *(const float4*)(wr+12);
            float2 w4 = *(const float2*)(wr+16);
            float v = xv[t];
            acc[0] +=v*w0.x; acc[1] +=v*w0.y; acc[2] +=v*w0.z; acc[3] +=v*w0.w;
            acc[4] +=v*w1.x; acc[5] +=v*w1.y; acc[6] +=v*w1.z; acc[7] +=v*w1.w;
            acc[8] +=v*w2.x; acc[9] +=v*w2.y; acc[10]+=v*w2.z; acc[11]+=v*w2.w;
            acc[12]+=v*w3.x; acc[13]+=v*w3.y; acc[14]+=v*w3.z; acc[15]+=v*w3.w;
            acc[16]+=v*w4.x; acc[17]+=v*w4.y;
        }
    }
    #pragma unroll
    for (int ch = 0; ch < 18; ++ch)
        g_offset[((b*NCH + ch)*HH + ho)*WW + wo] = acc[ch];
}

// ---------------------------------------------------------------------------
// Kernel 2: deformable conv as implicit GEMM.
// grid = B*H blocks (one 128-pixel row = M-tile 128), 512 threads.
// smem: full weight transposed to [tap][c][o] (147KB, loaded once/block),
//       val tile [c][pixel] (32KB), per-(tap,pixel) corner idx+weights (36KB).
// Per tap: fill val via bilinear gather, then 4x4 register-tiled GEMM
// (2x LDS.128 per 16 FFMA, conflict-free).
// ---------------------------------------------------------------------------
__global__ __launch_bounds__(512) void deform_kernel(
    const float* __restrict__ x,
    const float* __restrict__ wgt,   // [64,64,3,3]
    const float* __restrict__ bias,  // [64]
    float* __restrict__ out)         // [4,64,128,128]
{
    extern __shared__ float sm[];
    float* ws_s  = sm;                          // 36864 floats: [k][c][o]
    float* val_s = sm + 36864;                  // 8192 floats:  [c][p]
    int*   idx_s = (int*)(sm + 36864 + 8192);   // 4608 ints:    [k][p][4]
    float* cw_s  = sm + 36864 + 8192 + 4608;    // 4608 floats:  [k][p][4]

    int tid = threadIdx.x;
    int b   = blockIdx.x >> 7;
    int ho  = blockIdx.x & 127;

    // stage weight transposed: ws_s[(k*64+c)*64+o] = wgt[(o*64+c)*9+k]
    for (int i = tid; i < 36864; i += 512) {
        int o = i & 63, c = (i >> 6) & 63, k = i >> 12;
        ws_s[i] = wgt[(o*64 + c)*9 + k];
    }

    // precompute all 9 taps x 128 pixels corner data
    for (int i = tid; i < 9*128; i += 512) {
        int k = i >> 7;
        int p = i & 127;
        int ky = k / 3, kx = k - ky*3;
        const float* offp = g_offset + (((size_t)b*NCH + 2*k)*HH + ho)*WW + p;
        float offy = offp[0];
        float offx = offp[HWP];
        float py = (float)(ho - 1 + ky) + offy;
        float px = (float)(p  - 1 + kx) + offx;
        float fy0 = floorf(py), fx0 = floorf(px);
        int y0 = (int)fy0, x0 = (int)fx0;
        float wy1 = py - fy0, wx1 = px - fx0;
        float wy0 = 1.f - wy1, wx0 = 1.f - wx1;
        int y1 = y0 + 1, x1 = x0 + 1;
        float vy0 = ((unsigned)y0 < (unsigned)HH) ? 1.f : 0.f;
        float vy1 = ((unsigned)y1 < (unsigned)HH) ? 1.f : 0.f;
        float vx0 = ((unsigned)x0 < (unsigned)WW) ? 1.f : 0.f;
        float vx1 = ((unsigned)x1 < (unsigned)WW) ? 1.f : 0.f;
        int cy0 = min(max(y0,0),HH-1), cy1 = min(max(y1,0),HH-1);
        int cx0 = min(max(x0,0),WW-1), cx1 = min(max(x1,0),WW-1);
        int base = i*4;
        idx_s[base+0] = cy0*WW + cx0;  cw_s[base+0] = wy0*wx0*vy0*vx0;
        idx_s[base+1] = cy0*WW + cx1;  cw_s[base+1] = wy0*wx1*vy0*vx1;
        idx_s[base+2] = cy1*WW + cx0;  cw_s[base+2] = wy1*wx0*vy1*vx0;
        idx_s[base+3] = cy1*WW + cx1;  cw_s[base+3] = wy1*wx1*vy1*vx1;
    }
    __syncthreads();

    float acc[16];
    #pragma unroll
    for (int i = 0; i < 16; ++i) acc[i] = 0.f;

    int og = (tid & 15) << 2;   // output-channel group (4)
    int pg = (tid >> 4) << 2;   // pixel group (4)
    int pv = tid & 127;         // pixel for val fill
    int cb = tid >> 7;          // channel block 0..3 for val fill

    const float* xb = x + (size_t)b*CC*HWP;

    for (int k = 0; k < 9; ++k) {
        // --- fill val tile for this tap ---
        {
            int base = (k*128 + pv)*4;
            int   i0 = idx_s[base+0], i1 = idx_s[base+1],
                  i2 = idx_s[base+2], i3 = idx_s[base+3];
            float w0 = cw_s[base+0], w1 = cw_s[base+1],
                  w2 = cw_s[base+2], w3 = cw_s[base+3];
            #pragma unroll 4
            for (int ci = 0; ci < 16; ++ci) {
                int c = cb*16 + ci;
                const float* xp = xb + c*HWP;
                val_s[c*128 + pv] = w0*xp[i0] + w1*xp[i1] + w2*xp[i2] + w3*xp[i3];
            }
        }
        __syncthreads();

        // --- GEMM: acc[oj*4+pi] += val[c][pg+pi] * w[k][c][og+oj] ---
        const float* wk = ws_s + k*4096;
        #pragma unroll 8
        for (int c = 0; c < 64; ++c) {
            float4 av = *(const float4*)(val_s + c*128 + pg);
            float4 wv = *(const float4*)(wk + c*64 + og);
            acc[0]  += av.x*wv.x; acc[1]  += av.y*wv.x; acc[2]  += av.z*wv.x; acc[3]  += av.w*wv.x;
            acc[4]  += av.x*wv.y; acc[5]  += av.y*wv.y; acc[6]  += av.z*wv.y; acc[7]  += av.w*wv.y;
            acc[8]  += av.x*wv.z; acc[9]  += av.y*wv.z; acc[10] += av.z*wv.z; acc[11] += av.w*wv.z;
            acc[12] += av.x*wv.w; acc[13] += av.y*wv.w; acc[14] += av.z*wv.w; acc[15] += av.w*wv.w;
        }
        __syncthreads();   // val_s reused next tap
    }

    #pragma unroll
    for (int oj = 0; oj < 4; ++oj) {
        float bv = bias[og + oj];
        float4 r = make_float4(acc[oj*4+0]+bv, acc[oj*4+1]+bv,
                               acc[oj*4+2]+bv, acc[oj*4+3]+bv);
        *(float4*)(out + (((size_t)b*OO + og + oj)*HH + ho)*WW + pg) = r;
    }
}

static const int DEFORM_SMEM = (36864 + 8192 + 4608 + 4608) * 4;  // 217088 B

extern "C" void kernel_launch(void* const* d_in, const int* in_sizes, int n_in,
                              void* d_out, int out_size)
{
    const float* x    = (const float*)d_in[0];
    const float* ow   = (const float*)d_in[1];
    const float* ob   = (const float*)d_in[2];
    const float* wgt  = (const float*)d_in[3];
    const float* bias = (const float*)d_in[4];
    float* out = (float*)d_out;

    cudaFuncSetAttribute(deform_kernel,
                         cudaFuncAttributeMaxDynamicSharedMemorySize, DEFORM_SMEM);

    offset_conv_kernel<<<BB*HH, 128>>>(x, ow, ob);
    deform_kernel<<<BB*HH, 512, DEFORM_SMEM>>>(x, wgt, bias, out);
}

// round 2
// speedup vs baseline: 1.7387x; 1.7387x over previous
#include <cuda_runtime.h>

#define HH 128
#define WW 128
#define HWP (HH*WW)
#define CC 64
#define OO 64
#define BB 4
#define NCH 18   // 2*K*K offset channels

// scratch: offset conv output [B,18,H,W], transposed weight [k][c][o]
__device__ float g_offset[BB*NCH*HH*WW];
__device__ float g_wt[9*CC*OO];

__device__ __forceinline__ void cp_async16(void* smem, const void* gmem) {
    unsigned saddr = (unsigned)__cvta_generic_to_shared(smem);
    asm volatile("cp.async.cg.shared.global [%0], [%1], 16;\n" :: "r"(saddr), "l"(gmem));
}
#define CP_COMMIT() asm volatile("cp.async.commit_group;\n" ::: "memory")
#define CP_WAIT0()  asm volatile("cp.async.wait_group 0;\n" ::: "memory")

// ---------------------------------------------------------------------------
// Kernel 0: transpose weight [O,C,3,3] -> g_wt[(k*64+c)*64+o]  (runs once)
// ---------------------------------------------------------------------------
__global__ void wt_transpose_kernel(const float* __restrict__ wgt)
{
    int i = blockIdx.x * 256 + threadIdx.x;
    if (i < 9*CC*OO) {
        int o = i & 63, c = (i >> 6) & 63, k = i >> 12;
        g_wt[i] = wgt[(o*CC + c)*9 + k];
    }
}

// ---------------------------------------------------------------------------
// Kernel 1: offset = conv3x3(x, offset_w) + offset_b
// ---------------------------------------------------------------------------
__global__ __launch_bounds__(128) void offset_conv_kernel(
    const float* __restrict__ x,
    const float* __restrict__ ow,   // [18,64,3,3]
    const float* __restrict__ ob)   // [18]
{
    __shared__ float ws[576*20];    // [c*9+t][ch padded to 20]
    __shared__ float bs[NCH];
    int tid = threadIdx.x;

    for (int i = tid; i < 576*18; i += 128) {
        int ct = i / 18, ch = i - ct*18;
        ws[ct*20 + ch] = ow[ch*576 + ct];
    }
    if (tid < NCH) bs[tid] = ob[tid];
    __syncthreads();

    int b  = blockIdx.x >> 7;
    int ho = blockIdx.x & 127;
    int wo = tid;

    float acc[18];
    #pragma unroll
    for (int i = 0; i < 18; ++i) acc[i] = bs[i];

    const float* xb = x + (size_t)b*CC*HWP;

    for (int c = 0; c < CC; ++c) {
        const float* xc = xb + c*HWP;
        float xv[9];
        #pragma unroll
        for (int dy = 0; dy < 3; ++dy) {
            int y = ho - 1 + dy;
            bool vy = ((unsigned)y < (unsigned)HH);
            #pragma unroll
            for (int dx = 0; dx < 3; ++dx) {
                int xx = wo - 1 + dx;
                bool v = vy && ((unsigned)xx < (unsigned)WW);
                xv[dy*3+dx] = v ? xc[y*WW + xx] : 0.f;
            }
        }
        #pragma unroll
        for (int t = 0; t < 9; ++t) {
            const float* wr = ws + (c*9+t)*20;
            float4 w0 = *(const float4*)(wr);
            float4 w1 = *(const float4*)(wr+4);
            float4 w2 = *(const float4*)(wr+8);
            float4 w3 = *(const float4*)(wr+12);
            float2 w4 = *(const float2*)(wr+16);
            float v = xv[t];
            acc[0] +=v*w0.x; acc[1] +=v*w0.y; acc[2] +=v*w0.z; acc[3] +=v*w0.w;
            acc[4] +=v*w1.x; acc[5] +=v*w1.y; acc[6] +=v*w1.z; acc[7] +=v*w1.w;
            acc[8] +=v*w2.x; acc[9] +=v*w2.y; acc[10]+=v*w2.z; acc[11]+=v*w2.w;
            acc[12]+=v*w3.x; acc[13]+=v*w3.y; acc[14]+=v*w3.z; acc[15]+=v*w3.w;
            acc[16]+=v*w4.x; acc[17]+=v*w4.y;
        }
    }
    #pragma unroll
    for (int ch = 0; ch < 18; ++ch)
        g_offset[((b*NCH + ch)*HH + ho)*WW + wo] = acc[ch];
}

// ---------------------------------------------------------------------------
// Kernel 2: deformable conv, software-pipelined implicit GEMM.
// smem (105 KB): val[2][64][128] + wtap[2][64][64] (cp.async) + py/px[9][128]
// -> 2 CTAs/SM. One __syncthreads per tap; fill(k+1) + cp.async(k+1) overlap
// GEMM(k).
// ---------------------------------------------------------------------------
__global__ void __launch_bounds__(512, 2) deform_kernel(
    const float* __restrict__ x,
    const float* __restrict__ bias,  // [64]
    float* __restrict__ out)         // [4,64,128,128]
{
    extern __shared__ float sm[];
    float* val_s = sm;               // 2 * 8192
    float* wt_s  = sm + 16384;       // 2 * 4096
    float* pp_s  = sm + 24576;       // 9*128*2 = 2304
    // total 26880 floats = 107520 B

    int tid = threadIdx.x;
    int b   = blockIdx.x >> 7;
    int ho  = blockIdx.x & 127;

    // stage py/px for all 9 taps x 128 pixels
    for (int i = tid; i < 9*128; i += 512) {
        int k = i >> 7, p = i & 127;
        int ky = k / 3, kx = k - ky*3;
        const float* offp = g_offset + (((size_t)b*NCH + 2*k)*HH + ho)*WW + p;
        pp_s[i*2+0] = (float)(ho - 1 + ky) + offp[0];
        pp_s[i*2+1] = (float)(p  - 1 + kx) + offp[HWP];
    }

    // prefetch weight tile for tap 0
    cp_async16(wt_s + tid*8,     g_wt + tid*8);
    cp_async16(wt_s + tid*8 + 4, g_wt + tid*8 + 4);
    CP_COMMIT();

    __syncthreads();   // pp_s visible

    int og = (tid & 15) << 2;   // output-channel group (4)
    int pg = (tid >> 4) << 2;   // pixel group (4)
    int pv = tid & 127;         // pixel for val fill
    int cb = tid >> 7;          // channel block 0..3 for val fill
    const float* xb = x + (size_t)b*CC*HWP;

    // bilinear-gather fill of one val buffer for tap k
    auto fill = [&](int k, float* vbuf) {
        float py = pp_s[(k*128 + pv)*2 + 0];
        float px = pp_s[(k*128 + pv)*2 + 1];
        float fy0 = floorf(py), fx0 = floorf(px);
        int y0 = (int)fy0, x0 = (int)fx0;
        int y1 = y0 + 1,   x1 = x0 + 1;
        float wy1 = py - fy0, wx1 = px - fx0;
        float wy0 = 1.f - wy1, wx0 = 1.f - wx1;
        float vy0 = ((unsigned)y0 < (unsigned)HH) ? 1.f : 0.f;
        float vy1 = ((unsigned)y1 < (unsigned)HH) ? 1.f : 0.f;
        float vx0 = ((unsigned)x0 < (unsigned)WW) ? 1.f : 0.f;
        float vx1 = ((unsigned)x1 < (unsigned)WW) ? 1.f : 0.f;
        int cy0 = min(max(y0,0),HH-1), cy1 = min(max(y1,0),HH-1);
        int cx0 = min(max(x0,0),WW-1), cx1 = min(max(x1,0),WW-1);
        int   i0 = cy0*WW + cx0, i1 = cy0*WW + cx1,
              i2 = cy1*WW + cx0, i3 = cy1*WW + cx1;
        float w0 = wy0*wx0*vy0*vx0, w1 = wy0*wx1*vy0*vx1,
              w2 = wy1*wx0*vy1*vx0, w3 = wy1*wx1*vy1*vx1;
        const float* xp = xb + (size_t)(cb*16)*HWP;
        float* vp = vbuf + (cb*16)*128 + pv;
        #pragma unroll 4
        for (int ci = 0; ci < 16; ++ci) {
            vp[ci*128] = w0*xp[i0] + w1*xp[i1] + w2*xp[i2] + w3*xp[i3];
            xp += HWP;
        }
    };

    fill(0, val_s);   // val buffer 0 <- tap 0

    float acc[16];
    #pragma unroll
    for (int i = 0; i < 16; ++i) acc[i] = 0.f;

    for (int k = 0; k < 9; ++k) {
        CP_WAIT0();        // wt tile k landed (this thread's group)
        __syncthreads();   // val fill(k) + all cp.asyncs visible block-wide

        if (k < 8) {
            // prefetch weight tile k+1 (buffer no longer read: GEMM k-1 done)
            const float* src = g_wt + (k+1)*4096;
            float* dst = wt_s + ((k+1)&1)*4096;
            cp_async16(dst + tid*8,     src + tid*8);
            cp_async16(dst + tid*8 + 4, src + tid*8 + 4);
            CP_COMMIT();
            // fill other val buffer for tap k+1 (overlaps GEMM below)
            fill(k+1, val_s + ((k+1)&1)*8192);
        }

        // GEMM: acc[oj*4+pi] += val[c][pg+pi] * w[k][c][og+oj]
        const float* vk = val_s + (k&1)*8192;
        const float* wk = wt_s  + (k&1)*4096;
        #pragma unroll 8
        for (int c = 0; c < 64; ++c) {
            float4 av = *(const float4*)(vk + c*128 + pg);
            float4 wv = *(const float4*)(wk + c*64 + og);
            acc[0]  += av.x*wv.x; acc[1]  += av.y*wv.x; acc[2]  += av.z*wv.x; acc[3]  += av.w*wv.x;
            acc[4]  += av.x*wv.y; acc[5]  += av.y*wv.y; acc[6]  += av.z*wv.y; acc[7]  += av.w*wv.y;
            acc[8]  += av.x*wv.z; acc[9]  += av.y*wv.z; acc[10] += av.z*wv.z; acc[11] += av.w*wv.z;
            acc[12] += av.x*wv.w; acc[13] += av.y*wv.w; acc[14] += av.z*wv.w; acc[15] += av.w*wv.w;
        }
    }

    #pragma unroll
    for (int oj = 0; oj < 4; ++oj) {
        float bv = bias[og + oj];
        float4 r = make_float4(acc[oj*4+0]+bv, acc[oj*4+1]+bv,
                               acc[oj*4+2]+bv, acc[oj*4+3]+bv);
        *(float4*)(out + (((size_t)b*OO + og + oj)*HH + ho)*WW + pg) = r;
    }
}

static const int DEFORM_SMEM = 26880 * 4;  // 107520 B

extern "C" void kernel_launch(void* const* d_in, const int* in_sizes, int n_in,
                              void* d_out, int out_size)
{
    const float* x    = (const float*)d_in[0];
    const float* ow   = (const float*)d_in[1];
    const float* ob   = (const float*)d_in[2];
    const float* wgt  = (const float*)d_in[3];
    const float* bias = (const float*)d_in[4];
    float* out = (float*)d_out;

    cudaFuncSetAttribute(deform_kernel,
                         cudaFuncAttributeMaxDynamicSharedMemorySize, DEFORM_SMEM);

    wt_transpose_kernel<<<(9*CC*OO + 255)/256, 256>>>(wgt);
    offset_conv_kernel<<<BB*HH, 128>>>(x, ow, ob);
    deform_kernel<<<BB*HH, 512, DEFORM_SMEM>>>(x, bias, out);
}

// round 7
// speedup vs baseline: 2.4443x; 1.4058x over previous
#include <cuda_runtime.h>
#include <cuda_bf16.h>
#include <cstdint>

#define HH 128
#define WW 128
#define HWP (HH*WW)
#define CC 64
#define OO 64
#define BB 4
#define NCH 18

// scratch
__device__ float g_offset[BB*NCH*HH*WW];
// per tap: 64 o-rows x 128B (64 bf16 ch), XOR-swizzled within row
__device__ __nv_bfloat16 g_wt_hi[9*4096];
__device__ __nv_bfloat16 g_wt_lo[9*4096];

// ---------------- helpers ----------------
__device__ __forceinline__ void cp_async16(void* smem, const void* gmem) {
    unsigned saddr = (unsigned)__cvta_generic_to_shared(smem);
    asm volatile("cp.async.cg.shared.global [%0], [%1], 16;\n" :: "r"(saddr), "l"(gmem));
}
#define CP_COMMIT() asm volatile("cp.async.commit_group;\n" ::: "memory")
#define CP_WAIT0()  asm volatile("cp.async.wait_group 0;\n" ::: "memory")

__device__ __forceinline__ unsigned su32(const void* p) {
    unsigned a;
    asm("{ .reg .u64 t; cvta.to.shared.u64 t, %1; cvt.u32.u64 %0, t; }" : "=r"(a) : "l"(p));
    return a;
}
__device__ __forceinline__ void ldsm_x4(unsigned& r0, unsigned& r1, unsigned& r2, unsigned& r3, unsigned a) {
    asm volatile("ldmatrix.sync.aligned.m8n8.x4.shared.b16 {%0,%1,%2,%3}, [%4];"
                 : "=r"(r0), "=r"(r1), "=r"(r2), "=r"(r3) : "r"(a));
}
// NON-trans x2: correct for B stored [n][k] row-major (k contiguous)
__device__ __forceinline__ void ldsm_x2(unsigned& r0, unsigned& r1, unsigned a) {
    asm volatile("ldmatrix.sync.aligned.m8n8.x2.shared.b16 {%0,%1}, [%2];"
                 : "=r"(r0), "=r"(r1) : "r"(a));
}
__device__ __forceinline__ void mma16816(float* d, unsigned a0, unsigned a1, unsigned a2, unsigned a3,
                                         unsigned b0, unsigned b1) {
    asm volatile(
        "mma.sync.aligned.m16n8k16.row.col.f32.bf16.bf16.f32 "
        "{%0,%1,%2,%3}, {%4,%5,%6,%7}, {%8,%9}, {%0,%1,%2,%3};"
        : "+f"(d[0]), "+f"(d[1]), "+f"(d[2]), "+f"(d[3])
        : "r"(a0), "r"(a1), "r"(a2), "r"(a3), "r"(b0), "r"(b1));
}

// ---------------------------------------------------------------------------
// Kernel 0: split weight to bf16 hi/lo, transpose to [tap][o][c], XOR-swizzle
// ---------------------------------------------------------------------------
__global__ void wt_prep_kernel(const float* __restrict__ wgt)
{
    int i = blockIdx.x * 256 + threadIdx.x;
    if (i >= 9*64*64) return;
    int c = i & 63, o = (i >> 6) & 63, k = i >> 12;
    float w = wgt[(o*64 + c)*9 + k];
    __nv_bfloat16 hi = __float2bfloat16(w);
    __nv_bfloat16 lo = __float2bfloat16(w - __bfloat162float(hi));
    int off = (o*128 + c*2) ^ ((o & 7) << 4);
    g_wt_hi[k*4096 + (off >> 1)] = hi;
    g_wt_lo[k*4096 + (off >> 1)] = lo;
}

// ---------------------------------------------------------------------------
// Kernel 1: offset = conv3x3(x, offset_w) + offset_b  (unchanged)
// ---------------------------------------------------------------------------
__global__ __launch_bounds__(128) void offset_conv_kernel(
    const float* __restrict__ x,
    const float* __restrict__ ow,
    const float* __restrict__ ob)
{
    __shared__ float ws[576*20];
    __shared__ float bs[NCH];
    int tid = threadIdx.x;

    for (int i = tid; i < 576*18; i += 128) {
        int ct = i / 18, ch = i - ct*18;
        ws[ct*20 + ch] = ow[ch*576 + ct];
    }
    if (tid < NCH) bs[tid] = ob[tid];
    __syncthreads();

    int b  = blockIdx.x >> 7;
    int ho = blockIdx.x & 127;
    int wo = tid;

    float acc[18];
    #pragma unroll
    for (int i = 0; i < 18; ++i) acc[i] = bs[i];

    const float* xb = x + (size_t)b*CC*HWP;

    for (int c = 0; c < CC; ++c) {
        const float* xc = xb + c*HWP;
        float xv[9];
        #pragma unroll
        for (int dy = 0; dy < 3; ++dy) {
            int y = ho - 1 + dy;
            bool vy = ((unsigned)y < (unsigned)HH);
            #pragma unroll
            for (int dx = 0; dx < 3; ++dx) {
                int xx = wo - 1 + dx;
                bool v = vy && ((unsigned)xx < (unsigned)WW);
                xv[dy*3+dx] = v ? xc[y*WW + xx] : 0.f;
            }
        }
        #pragma unroll
        for (int t = 0; t < 9; ++t) {
            const float* wr = ws + (c*9+t)*20;
            float4 w0 = *(const float4*)(wr);
            float4 w1 = *(const float4*)(wr+4);
            float4 w2 = *(const float4*)(wr+8);
            float4 w3 = *(const float4*)(wr+12);
            float2 w4 = *(const float2*)(wr+16);
            float v = xv[t];
            acc[0] +=v*w0.x; acc[1] +=v*w0.y; acc[2] +=v*w0.z; acc[3] +=v*w0.w;
            acc[4] +=v*w1.x; acc[5] +=v*w1.y; acc[6] +=v*w1.z; acc[7] +=v*w1.w;
            acc[8] +=v*w2.x; acc[9] +=v*w2.y; acc[10]+=v*w2.z; acc[11]+=v*w2.w;
            acc[12]+=v*w3.x; acc[13]+=v*w3.y; acc[14]+=v*w3.z; acc[15]+=v*w3.w;
            acc[16]+=v*w4.x; acc[17]+=v*w4.y;
        }
    }
    #pragma unroll
    for (int ch = 0; ch < 18; ++ch)
        g_offset[((b*NCH + ch)*HH + ho)*WW + wo] = acc[ch];
}

// ---------------------------------------------------------------------------
// Kernel 2: deformable conv — HMMA bf16 (mma.sync m16n8k16) with hi/lo split.
// block = one (b,ho) row: M=128 px, N=64 o, K=9 taps x 64 ch x 3 terms.
// smem 105.5KB: val[2 st][hi,lo][128x128B] + wt[2 st][hi,lo][64x128B] + pp.
// 16 warps x (32x16) output tiles, 2 CTAs/SM.
// ---------------------------------------------------------------------------
#define SM_VAL   0        // stage*32768 + term*16384
#define SM_WT    65536    // stage*16384 + term*8192
#define SM_PP    98304    // 9*128*2 floats = 9216 B
#define DEFORM_SMEM (98304 + 9216)

__global__ void __launch_bounds__(512, 2) deform_kernel(
    const float* __restrict__ x,
    const float* __restrict__ bias,
    float* __restrict__ out)
{
    extern __shared__ char sm[];
    float* pp_s = (float*)(sm + SM_PP);

    int tid  = threadIdx.x;
    int wid  = tid >> 5;
    int lane = tid & 31;
    int b    = blockIdx.x >> 7;
    int ho   = blockIdx.x & 127;

    unsigned smb = su32(sm);

    // stage sampling positions
    for (int i = tid; i < 9*128; i += 512) {
        int k = i >> 7, p = i & 127;
        int ky = k / 3, kx = k - ky*3;
        const float* offp = g_offset + (((size_t)b*NCH + 2*k)*HH + ho)*WW + p;
        pp_s[i*2+0] = (float)(ho - 1 + ky) + offp[0];
        pp_s[i*2+1] = (float)(p  - 1 + kx) + offp[HWP];
    }

    // prefetch wt tap 0 into stage 0
    cp_async16(sm + SM_WT        + tid*16, (const char*)g_wt_hi + tid*16);
    cp_async16(sm + SM_WT + 8192 + tid*16, (const char*)g_wt_lo + tid*16);
    CP_COMMIT();

    // pp_s must be visible before fill(0) reads positions written by other threads
    __syncthreads();

    int pv = tid & 127;
    int cb = tid >> 7;
    const float* xb = x + (size_t)b*CC*HWP;

    int sA = pv*128 + cb*32;
    int sw0 = sA        ^ ((pv & 7) << 4);
    int sw1 = (sA + 16) ^ ((pv & 7) << 4);

    auto fill = [&](int k, int st) {
        float py = pp_s[(k*128 + pv)*2 + 0];
        float px = pp_s[(k*128 + pv)*2 + 1];
        float fy0 = floorf(py), fx0 = floorf(px);
        int y0 = (int)fy0, x0 = (int)fx0;
        int y1 = y0 + 1,   x1 = x0 + 1;
        float wy1 = py - fy0, wx1 = px - fx0;
        float wy0 = 1.f - wy1, wx0 = 1.f - wx1;
        float vy0 = ((unsigned)y0 < (unsigned)HH) ? 1.f : 0.f;
        float vy1 = ((unsigned)y1 < (unsigned)HH) ? 1.f : 0.f;
        float vx0 = ((unsigned)x0 < (unsigned)WW) ? 1.f : 0.f;
        float vx1 = ((unsigned)x1 < (unsigned)WW) ? 1.f : 0.f;
        int cy0 = min(max(y0,0),HH-1), cy1 = min(max(y1,0),HH-1);
        int cx0 = min(max(x0,0),WW-1), cx1 = min(max(x1,0),WW-1);
        int   i0 = cy0*WW + cx0, i1 = cy0*WW + cx1,
              i2 = cy1*WW + cx0, i3 = cy1*WW + cx1;
        float w0 = wy0*wx0*vy0*vx0, w1 = wy0*wx1*vy0*vx1,
              w2 = wy1*wx0*vy1*vx0, w3 = wy1*wx1*vy1*vx1;

        char* vh = sm + SM_VAL + st*32768;
        char* vl = vh + 16384;
        const float* xp = xb + (size_t)(cb*16)*HWP;

        #pragma unroll
        for (int h = 0; h < 2; ++h) {
            unsigned hq[4], lq[4];
            #pragma unroll
            for (int j = 0; j < 4; ++j) {
                const float* pa = xp + (size_t)(h*8 + 2*j)*HWP;
                const float* pb = pa + HWP;
                float v0 = w0*pa[i0] + w1*pa[i1] + w2*pa[i2] + w3*pa[i3];
                float v1 = w0*pb[i0] + w1*pb[i1] + w2*pb[i2] + w3*pb[i3];
                __nv_bfloat162 h2 = __floats2bfloat162_rn(v0, v1);
                float r0 = v0 - __bfloat162float(__low2bfloat16(h2));
                float r1 = v1 - __bfloat162float(__high2bfloat16(h2));
                __nv_bfloat162 l2 = __floats2bfloat162_rn(r0, r1);
                hq[j] = reinterpret_cast<unsigned&>(h2);
                lq[j] = reinterpret_cast<unsigned&>(l2);
            }
            int swo = h ? sw1 : sw0;
            *(uint4*)(vh + swo) = make_uint4(hq[0],hq[1],hq[2],hq[3]);
            *(uint4*)(vl + swo) = make_uint4(lq[0],lq[1],lq[2],lq[3]);
        }
    };

    fill(0, 0);
    CP_WAIT0();
    __syncthreads();

    // per-thread MMA fragment addressing constants
    int mw = wid & 3, nw = wid >> 2;
    int mr = lane & 7, mm = lane >> 3;       // A: matrix idx 0..3
    int pixA = mw*32 + (mm & 1)*8 + mr;
    unsigned aRow0 = (unsigned)pixA*128;
    unsigned aRow1 = aRow0 + 16*128;
    unsigned sxa   = (unsigned)((pixA & 7) << 4);
    unsigned hm    = (unsigned)((mm >> 1) * 16);
    int m2 = (lane >> 3) & 1;                // B: matrix idx (non-trans x2)
    int oR = nw*16 + mr;
    unsigned bRow0 = (unsigned)oR*128;
    unsigned bRow1 = bRow0 + 8*128;
    unsigned sxb   = (unsigned)((oR & 7) << 4);
    unsigned bm    = (unsigned)(m2 * 16);

    float acc[16];
    #pragma unroll
    for (int i = 0; i < 16; ++i) acc[i] = 0.f;

    for (int k = 0; k < 9; ++k) {
        int st = k & 1;
        if (k < 8) {
            int nb = st ^ 1;
            const char* sh = (const char*)g_wt_hi + (k+1)*8192;
            const char* sl = (const char*)g_wt_lo + (k+1)*8192;
            cp_async16(sm + SM_WT + nb*16384        + tid*16, sh + tid*16);
            cp_async16(sm + SM_WT + nb*16384 + 8192 + tid*16, sl + tid*16);
            CP_COMMIT();
            fill(k + 1, nb);
        }

        // ---- MMA for tap k from stage st ----
        unsigned vh = smb + SM_VAL + st*32768;
        unsigned vl = vh + 16384;
        unsigned wh = smb + SM_WT + st*16384;
        unsigned wl = wh + 8192;

        #pragma unroll
        for (int kc = 0; kc < 4; ++kc) {
            unsigned la = ((unsigned)(kc*32) + hm) ^ sxa;
            unsigned lb = ((unsigned)(kc*32) + bm) ^ sxb;
            unsigned bh0a, bh0b, bh1a, bh1b, bl0a, bl0b, bl1a, bl1b;
            ldsm_x2(bh0a, bh0b, wh + bRow0 + lb);
            ldsm_x2(bh1a, bh1b, wh + bRow1 + lb);
            ldsm_x2(bl0a, bl0b, wl + bRow0 + lb);
            ldsm_x2(bl1a, bl1b, wl + bRow1 + lb);
            {
                unsigned a0,a1,a2,a3, c0,c1,c2,c3;
                ldsm_x4(a0,a1,a2,a3, vh + aRow0 + la);
                ldsm_x4(c0,c1,c2,c3, vh + aRow1 + la);
                // Ah x Bh
                mma16816(acc+0,  a0,a1,a2,a3, bh0a,bh0b);
                mma16816(acc+4,  a0,a1,a2,a3, bh1a,bh1b);
                mma16816(acc+8,  c0,c1,c2,c3, bh0a,bh0b);
                mma16816(acc+12, c0,c1,c2,c3, bh1a,bh1b);
                // Ah x Bl
                mma16816(acc+0,  a0,a1,a2,a3, bl0a,bl0b);
                mma16816(acc+4,  a0,a1,a2,a3, bl1a,bl1b);
                mma16816(acc+8,  c0,c1,c2,c3, bl0a,bl0b);
                mma16816(acc+12, c0,c1,c2,c3, bl1a,bl1b);
            }
            {
                unsigned a0,a1,a2,a3, c0,c1,c2,c3;
                ldsm_x4(a0,a1,a2,a3, vl + aRow0 + la);
                ldsm_x4(c0,c1,c2,c3, vl + aRow1 + la);
                // Al x Bh
                mma16816(acc+0,  a0,a1,a2,a3, bh0a,bh0b);
                mma16816(acc+4,  a0,a1,a2,a3, bh1a,bh1b);
                mma16816(acc+8,  c0,c1,c2,c3, bh0a,bh0b);
                mma16816(acc+12, c0,c1,c2,c3, bh1a,bh1b);
            }
        }

        if (k < 8) CP_WAIT0();
        __syncthreads();
    }

    // ---- epilogue ----
    int g  = lane >> 2, tg = lane & 3;
    float* ob = out + (size_t)b*OO*HWP + (size_t)ho*WW;
    #pragma unroll
    for (int mi = 0; mi < 2; ++mi) {
        #pragma unroll
        for (int ni = 0; ni < 2; ++ni) {
            int p0 = mw*32 + mi*16 + g;
            int o0 = nw*16 + ni*8 + tg*2;
            float bv0 = __ldg(bias + o0), bv1 = __ldg(bias + o0 + 1);
            float* q0 = ob + (size_t)o0*HWP;
            float* q1 = q0 + HWP;
            const float* a = acc + (mi*2 + ni)*4;
            q0[p0]     = a[0] + bv0;
            q1[p0]     = a[1] + bv1;
            q0[p0 + 8] = a[2] + bv0;
            q1[p0 + 8] = a[3] + bv1;
        }
    }
}

extern "C" void kernel_launch(void* const* d_in, const int* in_sizes, int n_in,
                              void* d_out, int out_size)
{
    const float* x    = (const float*)d_in[0];
    const float* ow   = (const float*)d_in[1];
    const float* ob   = (const float*)d_in[2];
    const float* wgt  = (const float*)d_in[3];
    const float* bias = (const float*)d_in[4];
    float* out = (float*)d_out;

    cudaFuncSetAttribute(deform_kernel,
                         cudaFuncAttributeMaxDynamicSharedMemorySize, DEFORM_SMEM);

    wt_prep_kernel<<<(9*64*64 + 255)/256, 256>>>(wgt);
    offset_conv_kernel<<<BB*HH, 128>>>(x, ow, ob);
    deform_kernel<<<BB*HH, 512, DEFORM_SMEM>>>(x, bias, out);
}

// round 9
// speedup vs baseline: 3.2449x; 1.3275x over previous
#include <cuda_runtime.h>
#include <cuda_bf16.h>
#include <cstdint>

#define HH 128
#define WW 128
#define HWP (HH*WW)
#define CC 64
#define OO 64
#define BB 4
#define NCH 18

// scratch
__device__ float g_offset[BB*NCH*HH*WW];
// deform weights per tap: 64 o-rows x 128B (64 bf16 ch), XOR-swizzled within row
__device__ __nv_bfloat16 g_wt_hi[9*4096];
__device__ __nv_bfloat16 g_wt_lo[9*4096];
// offset-conv weights per tap: 24 o-rows (18 real + 6 zero) x 128B, swizzled
__device__ __nv_bfloat16 g_ow_hi[9*24*64];
__device__ __nv_bfloat16 g_ow_lo[9*24*64];

// ---------------- helpers ----------------
__device__ __forceinline__ void cp_async16(void* smem, const void* gmem) {
    unsigned saddr = (unsigned)__cvta_generic_to_shared(smem);
    asm volatile("cp.async.cg.shared.global [%0], [%1], 16;\n" :: "r"(saddr), "l"(gmem));
}
#define CP_COMMIT() asm volatile("cp.async.commit_group;\n" ::: "memory")
#define CP_WAIT0()  asm volatile("cp.async.wait_group 0;\n" ::: "memory")

__device__ __forceinline__ unsigned su32(const void* p) {
    unsigned a;
    asm("{ .reg .u64 t; cvta.to.shared.u64 t, %1; cvt.u32.u64 %0, t; }" : "=r"(a) : "l"(p));
    return a;
}
__device__ __forceinline__ void ldsm_x4(unsigned& r0, unsigned& r1, unsigned& r2, unsigned& r3, unsigned a) {
    asm volatile("ldmatrix.sync.aligned.m8n8.x4.shared.b16 {%0,%1,%2,%3}, [%4];"
                 : "=r"(r0), "=r"(r1), "=r"(r2), "=r"(r3) : "r"(a));
}
// NON-trans x2: correct for B stored [n][k] row-major (k contiguous)
__device__ __forceinline__ void ldsm_x2(unsigned& r0, unsigned& r1, unsigned a) {
    asm volatile("ldmatrix.sync.aligned.m8n8.x2.shared.b16 {%0,%1}, [%2];"
                 : "=r"(r0), "=r"(r1) : "r"(a));
}
__device__ __forceinline__ void mma16816(float* d, unsigned a0, unsigned a1, unsigned a2, unsigned a3,
                                         unsigned b0, unsigned b1) {
    asm volatile(
        "mma.sync.aligned.m16n8k16.row.col.f32.bf16.bf16.f32 "
        "{%0,%1,%2,%3}, {%4,%5,%6,%7}, {%8,%9}, {%0,%1,%2,%3};"
        : "+f"(d[0]), "+f"(d[1]), "+f"(d[2]), "+f"(d[3])
        : "r"(a0), "r"(a1), "r"(a2), "r"(a3), "r"(b0), "r"(b1));
}

// ---------------------------------------------------------------------------
// Kernel 0a: split deform weight to bf16 hi/lo, [tap][o][c], XOR-swizzle
// ---------------------------------------------------------------------------
__global__ void wt_prep_kernel(const float* __restrict__ wgt)
{
    int i = blockIdx.x * 256 + threadIdx.x;
    if (i >= 9*64*64) return;
    int c = i & 63, o = (i >> 6) & 63, k = i >> 12;
    float w = wgt[(o*64 + c)*9 + k];
    __nv_bfloat16 hi = __float2bfloat16(w);
    __nv_bfloat16 lo = __float2bfloat16(w - __bfloat162float(hi));
    int off = (o*128 + c*2) ^ ((o & 7) << 4);
    g_wt_hi[k*4096 + (off >> 1)] = hi;
    g_wt_lo[k*4096 + (off >> 1)] = lo;
}

// ---------------------------------------------------------------------------
// Kernel 0b: split offset weight [18,64,3,3] -> [tap][24 rows][64 c] hi/lo
// rows 18..23 zero.
// ---------------------------------------------------------------------------
__global__ void wt2_prep_kernel(const float* __restrict__ ow)
{
    int i = blockIdx.x * 256 + threadIdx.x;
    if (i >= 9*24*64) return;
    int c = i & 63;
    int o = (i >> 6) % 24;
    int k = i / (24*64);
    float w = (o < 18) ? ow[(o*64 + c)*9 + k] : 0.f;
    __nv_bfloat16 hi = __float2bfloat16(w);
    __nv_bfloat16 lo = __float2bfloat16(w - __bfloat162float(hi));
    int off = (o*128 + c*2) ^ ((o & 7) << 4);
    g_ow_hi[k*1536 + (off >> 1)] = hi;
    g_ow_lo[k*1536 + (off >> 1)] = lo;
}

// ---------------------------------------------------------------------------
// Kernel 1: offset conv3x3 via HMMA.
// Block = 2 output rows (M=256 px), 512 threads (16 warps, m16n24 tiles each).
// A: 4 x-rows (ho0-1..ho0+2) x 64ch, hi/lo bf16, [plane][w'=w+1][c] w/ zero
// pad cols w'=0,129. All 9 taps read from these planes by address shift —
// single fill, no per-tap syncs.
// ---------------------------------------------------------------------------
#define PLANE 16640                  // 130 rows * 128 B
#define SMO_A_LO (4*PLANE)           // 66560
#define SMO_B    (8*PLANE)           // 133120 ; B: hi 27648 + lo 27648
#define OFFK_SMEM (133120 + 55296)   // 188416 B

__global__ void __launch_bounds__(512, 1) offset_mma_kernel(
    const float* __restrict__ x,
    const float* __restrict__ ob)    // [18] bias
{
    extern __shared__ char sm[];
    int tid  = threadIdx.x;
    int wid  = tid >> 5;
    int lane = tid & 31;
    int b    = blockIdx.x >> 6;
    int ho0  = (blockIdx.x & 63) << 1;

    unsigned smb = su32(sm);
    unsigned Ahi = smb, Alo = smb + SMO_A_LO;
    unsigned Bhi = smb + SMO_B, Blo = Bhi + 27648;

    // B via cp.async
    for (int off = tid*16; off < 27648; off += 8192) {
        cp_async16(sm + SMO_B         + off, (const char*)g_ow_hi + off);
        cp_async16(sm + SMO_B + 27648 + off, (const char*)g_ow_lo + off);
    }
    CP_COMMIT();

    // A fill: 4 planes x 32 c-pairs x 128 w  (32 items/thread)
    const float* xb = x + (size_t)b*CC*HWP;
    for (int i = tid; i < 4*32*128; i += 512) {
        int w  = i & 127;
        int cp = (i >> 7) & 31;
        int j  = i >> 12;
        int row = ho0 - 1 + j;
        float v0 = 0.f, v1 = 0.f;
        if ((unsigned)row < (unsigned)HH) {
            v0 = xb[((size_t)(2*cp)  *HH + row)*WW + w];
            v1 = xb[((size_t)(2*cp+1)*HH + row)*WW + w];
        }
        __nv_bfloat162 h2 = __floats2bfloat162_rn(v0, v1);
        float r0 = v0 - __bfloat162float(__low2bfloat16(h2));
        float r1 = v1 - __bfloat162float(__high2bfloat16(h2));
        __nv_bfloat162 l2 = __floats2bfloat162_rn(r0, r1);
        int wp  = w + 1;
        int col = (4*cp) ^ ((wp & 7) << 4);
        int byt = j*PLANE + wp*128 + col;
        *(__nv_bfloat162*)(sm + byt)            = h2;
        *(__nv_bfloat162*)(sm + SMO_A_LO + byt) = l2;
    }
    // zero edge columns w'=0 and w'=129
    for (int i = tid; i < 4*2*32; i += 512) {
        int cp = i & 31, e = (i >> 5) & 1, j = i >> 6;
        int wp = e ? 129 : 0;
        int col = (4*cp) ^ ((wp & 7) << 4);
        int byt = j*PLANE + wp*128 + col;
        *(unsigned*)(sm + byt)            = 0u;
        *(unsigned*)(sm + SMO_A_LO + byt) = 0u;
    }
    CP_WAIT0();
    __syncthreads();

    // fragment addressing
    int r  = wid >> 3;             // image row within block (0/1)
    int pb = (wid & 7) * 16;       // pixel base within row
    int mr = lane & 7, mm = lane >> 3;
    int p_frag = pb + (mm & 1)*8 + mr;
    unsigned hm = (unsigned)((mm >> 1) * 16);
    unsigned bm = (unsigned)(((lane >> 3) & 1) * 16);

    float acc[12];
    #pragma unroll
    for (int i = 0; i < 12; ++i) acc[i] = 0.f;

    #pragma unroll
    for (int k = 0; k < 9; ++k) {
        int ky = k / 3, kx = k - 3*ky;
        unsigned aPlaneH = Ahi + (unsigned)((r + ky)*PLANE);
        unsigned aPlaneL = Alo + (unsigned)((r + ky)*PLANE);
        int roww = p_frag + kx;
        unsigned arow = (unsigned)(roww*128);
        unsigned sx   = (unsigned)((roww & 7) << 4);
        unsigned bk   = (unsigned)(k*3072);
        #pragma unroll
        for (int kc = 0; kc < 4; ++kc) {
            unsigned la = ((unsigned)(kc*32) + hm) ^ sx;
            unsigned ah0,ah1,ah2,ah3, al0,al1,al2,al3;
            ldsm_x4(ah0,ah1,ah2,ah3, aPlaneH + arow + la);
            ldsm_x4(al0,al1,al2,al3, aPlaneL + arow + la);
            unsigned lb = ((unsigned)(kc*32) + bm) ^ ((unsigned)(mr << 4));
            #pragma unroll
            for (int nt = 0; nt < 3; ++nt) {
                unsigned brow = bk + (unsigned)(nt*1024 + mr*128);
                unsigned bh0, bh1, bl0, bl1;
                ldsm_x2(bh0, bh1, Bhi + brow + lb);
                ldsm_x2(bl0, bl1, Blo + brow + lb);
                mma16816(acc + nt*4, ah0,ah1,ah2,ah3, bh0,bh1);
                mma16816(acc + nt*4, ah0,ah1,ah2,ah3, bl0,bl1);
                mma16816(acc + nt*4, al0,al1,al2,al3, bh0,bh1);
            }
        }
    }

    // epilogue: write 18 offset channels (+bias)
    int g = lane >> 2, tg = lane & 3;
    int how = ho0 + r;
    #pragma unroll
    for (int nt = 0; nt < 3; ++nt) {
        #pragma unroll
        for (int sub = 0; sub < 2; ++sub) {
            int o = nt*8 + tg*2 + sub;
            if (o < NCH) {
                float bv = __ldg(ob + o);
                float* q = g_offset + (((size_t)b*NCH + o)*HH + how)*WW;
                q[pb + g]     = acc[nt*4 + sub]     + bv;
                q[pb + g + 8] = acc[nt*4 + 2 + sub] + bv;
            }
        }
    }
}

// ---------------------------------------------------------------------------
// Kernel 2: deformable conv — HMMA bf16 (mma.sync m16n8k16) with hi/lo split.
// (unchanged from R7 passing version)
// ---------------------------------------------------------------------------
#define SM_VAL   0        // stage*32768 + term*16384
#define SM_WT    65536    // stage*16384 + term*8192
#define SM_PP    98304    // 9*128*2 floats = 9216 B
#define DEFORM_SMEM (98304 + 9216)

__global__ void __launch_bounds__(512, 2) deform_kernel(
    const float* __restrict__ x,
    const float* __restrict__ bias,
    float* __restrict__ out)
{
    extern __shared__ char sm[];
    float* pp_s = (float*)(sm + SM_PP);

    int tid  = threadIdx.x;
    int wid  = tid >> 5;
    int lane = tid & 31;
    int b    = blockIdx.x >> 7;
    int ho   = blockIdx.x & 127;

    unsigned smb = su32(sm);

    for (int i = tid; i < 9*128; i += 512) {
        int k = i >> 7, p = i & 127;
        int ky = k / 3, kx = k - ky*3;
        const float* offp = g_offset + (((size_t)b*NCH + 2*k)*HH + ho)*WW + p;
        pp_s[i*2+0] = (float)(ho - 1 + ky) + offp[0];
        pp_s[i*2+1] = (float)(p  - 1 + kx) + offp[HWP];
    }

    cp_async16(sm + SM_WT        + tid*16, (const char*)g_wt_hi + tid*16);
    cp_async16(sm + SM_WT + 8192 + tid*16, (const char*)g_wt_lo + tid*16);
    CP_COMMIT();

    __syncthreads();

    int pv = tid & 127;
    int cb = tid >> 7;
    const float* xb = x + (size_t)b*CC*HWP;

    int sA = pv*128 + cb*32;
    int sw0 = sA        ^ ((pv & 7) << 4);
    int sw1 = (sA + 16) ^ ((pv & 7) << 4);

    auto fill = [&](int k, int st) {
        float py = pp_s[(k*128 + pv)*2 + 0];
        float px = pp_s[(k*128 + pv)*2 + 1];
        float fy0 = floorf(py), fx0 = floorf(px);
        int y0 = (int)fy0, x0 = (int)fx0;
        int y1 = y0 + 1,   x1 = x0 + 1;
        float wy1 = py - fy0, wx1 = px - fx0;
        float wy0 = 1.f - wy1, wx0 = 1.f - wx1;
        float vy0 = ((unsigned)y0 < (unsigned)HH) ? 1.f : 0.f;
        float vy1 = ((unsigned)y1 < (unsigned)HH) ? 1.f : 0.f;
        float vx0 = ((unsigned)x0 < (unsigned)WW) ? 1.f : 0.f;
        float vx1 = ((unsigned)x1 < (unsigned)WW) ? 1.f : 0.f;
        int cy0 = min(max(y0,0),HH-1), cy1 = min(max(y1,0),HH-1);
        int cx0 = min(max(x0,0),WW-1), cx1 = min(max(x1,0),WW-1);
        int   i0 = cy0*WW + cx0, i1 = cy0*WW + cx1,
              i2 = cy1*WW + cx0, i3 = cy1*WW + cx1;
        float w0 = wy0*wx0*vy0*vx0, w1 = wy0*wx1*vy0*vx1,
              w2 = wy1*wx0*vy1*vx0, w3 = wy1*wx1*vy1*vx1;

        char* vh = sm + SM_VAL + st*32768;
        char* vl = vh + 16384;
        const float* xp = xb + (size_t)(cb*16)*HWP;

        #pragma unroll
        for (int h = 0; h < 2; ++h) {
            unsigned hq[4], lq[4];
            #pragma unroll
            for (int j = 0; j < 4; ++j) {
                const float* pa = xp + (size_t)(h*8 + 2*j)*HWP;
                const float* pb = pa + HWP;
                float v0 = w0*pa[i0] + w1*pa[i1] + w2*pa[i2] + w3*pa[i3];
                float v1 = w0*pb[i0] + w1*pb[i1] + w2*pb[i2] + w3*pb[i3];
                __nv_bfloat162 h2 = __floats2bfloat162_rn(v0, v1);
                float r0 = v0 - __bfloat162float(__low2bfloat16(h2));
                float r1 = v1 - __bfloat162float(__high2bfloat16(h2));
                __nv_bfloat162 l2 = __floats2bfloat162_rn(r0, r1);
                hq[j] = reinterpret_cast<unsigned&>(h2);
                lq[j] = reinterpret_cast<unsigned&>(l2);
            }
            int swo = h ? sw1 : sw0;
            *(uint4*)(vh + swo) = make_uint4(hq[0],hq[1],hq[2],hq[3]);
            *(uint4*)(vl + swo) = make_uint4(lq[0],lq[1],lq[2],lq[3]);
        }
    };

    fill(0, 0);
    CP_WAIT0();
    __syncthreads();

    int mw = wid & 3, nw = wid >> 2;
    int mr = lane & 7, mm = lane >> 3;
    int pixA = mw*32 + (mm & 1)*8 + mr;
    unsigned aRow0 = (unsigned)pixA*128;
    unsigned aRow1 = aRow0 + 16*128;
    unsigned sxa   = (unsigned)((pixA & 7) << 4);
    unsigned hm    = (unsigned)((mm >> 1) * 16);
    int m2 = (lane >> 3) & 1;
    int oR = nw*16 + mr;
    unsigned bRow0 = (unsigned)oR*128;
    unsigned bRow1 = bRow0 + 8*128;
    unsigned sxb   = (unsigned)((oR & 7) << 4);
    unsigned bm    = (unsigned)(m2 * 16);

    float acc[16];
    #pragma unroll
    for (int i = 0; i < 16; ++i) acc[i] = 0.f;

    for (int k = 0; k < 9; ++k) {
        int st = k & 1;
        if (k < 8) {
            int nb = st ^ 1;
            const char* sh = (const char*)g_wt_hi + (k+1)*8192;
            const char* sl = (const char*)g_wt_lo + (k+1)*8192;
            cp_async16(sm + SM_WT + nb*16384        + tid*16, sh + tid*16);
            cp_async16(sm + SM_WT + nb*16384 + 8192 + tid*16, sl + tid*16);
            CP_COMMIT();
            fill(k + 1, nb);
        }

        unsigned vh = smb + SM_VAL + st*32768;
        unsigned vl = vh + 16384;
        unsigned wh = smb + SM_WT + st*16384;
        unsigned wl = wh + 8192;

        #pragma unroll
        for (int kc = 0; kc < 4; ++kc) {
            unsigned la = ((unsigned)(kc*32) + hm) ^ sxa;
            unsigned lb = ((unsigned)(kc*32) + bm) ^ sxb;
            unsigned bh0a, bh0b, bh1a, bh1b, bl0a, bl0b, bl1a, bl1b;
            ldsm_x2(bh0a, bh0b, wh + bRow0 + lb);
            ldsm_x2(bh1a, bh1b, wh + bRow1 + lb);
            ldsm_x2(bl0a, bl0b, wl + bRow0 + lb);
            ldsm_x2(bl1a, bl1b, wl + bRow1 + lb);
            {
                unsigned a0,a1,a2,a3, c0,c1,c2,c3;
                ldsm_x4(a0,a1,a2,a3, vh + aRow0 + la);
                ldsm_x4(c0,c1,c2,c3, vh + aRow1 + la);
                mma16816(acc+0,  a0,a1,a2,a3, bh0a,bh0b);
                mma16816(acc+4,  a0,a1,a2,a3, bh1a,bh1b);
                mma16816(acc+8,  c0,c1,c2,c3, bh0a,bh0b);
                mma16816(acc+12, c0,c1,c2,c3, bh1a,bh1b);
                mma16816(acc+0,  a0,a1,a2,a3, bl0a,bl0b);
                mma16816(acc+4,  a0,a1,a2,a3, bl1a,bl1b);
                mma16816(acc+8,  c0,c1,c2,c3, bl0a,bl0b);
                mma16816(acc+12, c0,c1,c2,c3, bl1a,bl1b);
            }
            {
                unsigned a0,a1,a2,a3, c0,c1,c2,c3;
                ldsm_x4(a0,a1,a2,a3, vl + aRow0 + la);
                ldsm_x4(c0,c1,c2,c3, vl + aRow1 + la);
                mma16816(acc+0,  a0,a1,a2,a3, bh0a,bh0b);
                mma16816(acc+4,  a0,a1,a2,a3, bh1a,bh1b);
                mma16816(acc+8,  c0,c1,c2,c3, bh0a,bh0b);
                mma16816(acc+12, c0,c1,c2,c3, bh1a,bh1b);
            }
        }

        if (k < 8) CP_WAIT0();
        __syncthreads();
    }

    int g  = lane >> 2, tg = lane & 3;
    float* ob = out + (size_t)b*OO*HWP + (size_t)ho*WW;
    #pragma unroll
    for (int mi = 0; mi < 2; ++mi) {
        #pragma unroll
        for (int ni = 0; ni < 2; ++ni) {
            int p0 = mw*32 + mi*16 + g;
            int o0 = nw*16 + ni*8 + tg*2;
            float bv0 = __ldg(bias + o0), bv1 = __ldg(bias + o0 + 1);
            float* q0 = ob + (size_t)o0*HWP;
            float* q1 = q0 + HWP;
            const float* a = acc + (mi*2 + ni)*4;
            q0[p0]     = a[0] + bv0;
            q1[p0]     = a[1] + bv1;
            q0[p0 + 8] = a[2] + bv0;
            q1[p0 + 8] = a[3] + bv1;
        }
    }
}

extern "C" void kernel_launch(void* const* d_in, const int* in_sizes, int n_in,
                              void* d_out, int out_size)
{
    const float* x    = (const float*)d_in[0];
    const float* ow   = (const float*)d_in[1];
    const float* ob   = (const float*)d_in[2];
    const float* wgt  = (const float*)d_in[3];
    const float* bias = (const float*)d_in[4];
    float* out = (float*)d_out;

    cudaFuncSetAttribute(deform_kernel,
                         cudaFuncAttributeMaxDynamicSharedMemorySize, DEFORM_SMEM);
    cudaFuncSetAttribute(offset_mma_kernel,
                         cudaFuncAttributeMaxDynamicSharedMemorySize, OFFK_SMEM);

    wt_prep_kernel<<<(9*64*64 + 255)/256, 256>>>(wgt);
    wt2_prep_kernel<<<(9*24*64 + 255)/256, 256>>>(ow);
    offset_mma_kernel<<<BB*64, 512, OFFK_SMEM>>>(x, ob);
    deform_kernel<<<BB*HH, 512, DEFORM_SMEM>>>(x, bias, out);
}

// round 10
// speedup vs baseline: 4.5065x; 1.3888x over previous
#include <cuda_runtime.h>
#include <cuda_bf16.h>
#include <cuda_fp16.h>
#include <cstdint>

#define HH 128
#define WW 128
#define HWP (HH*WW)
#define CC 64
#define OO 64
#define BB 4
#define NCH 18

// scratch
__device__ float g_offset[BB*NCH*HH*WW];
// deform weights per tap: 64 o-rows x 128B (64 fp16 ch), XOR-swizzled within row
__device__ __half g_wt[9*4096];
// offset-conv weights per tap: 24 o-rows (18 real + 6 zero) x 128B, swizzled (bf16 hi/lo)
__device__ __nv_bfloat16 g_ow_hi[9*24*64];
__device__ __nv_bfloat16 g_ow_lo[9*24*64];

// ---------------- helpers ----------------
__device__ __forceinline__ void cp_async16(void* smem, const void* gmem) {
    unsigned saddr = (unsigned)__cvta_generic_to_shared(smem);
    asm volatile("cp.async.cg.shared.global [%0], [%1], 16;\n" :: "r"(saddr), "l"(gmem));
}
#define CP_COMMIT() asm volatile("cp.async.commit_group;\n" ::: "memory")
#define CP_WAIT0()  asm volatile("cp.async.wait_group 0;\n" ::: "memory")

__device__ __forceinline__ unsigned su32(const void* p) {
    unsigned a;
    asm("{ .reg .u64 t; cvta.to.shared.u64 t, %1; cvt.u32.u64 %0, t; }" : "=r"(a) : "l"(p));
    return a;
}
__device__ __forceinline__ void ldsm_x4(unsigned& r0, unsigned& r1, unsigned& r2, unsigned& r3, unsigned a) {
    asm volatile("ldmatrix.sync.aligned.m8n8.x4.shared.b16 {%0,%1,%2,%3}, [%4];"
                 : "=r"(r0), "=r"(r1), "=r"(r2), "=r"(r3) : "r"(a));
}
__device__ __forceinline__ void ldsm_x2(unsigned& r0, unsigned& r1, unsigned a) {
    asm volatile("ldmatrix.sync.aligned.m8n8.x2.shared.b16 {%0,%1}, [%2];"
                 : "=r"(r0), "=r"(r1) : "r"(a));
}
// bf16 MMA (offset conv)
__device__ __forceinline__ void mma16816(float* d, unsigned a0, unsigned a1, unsigned a2, unsigned a3,
                                         unsigned b0, unsigned b1) {
    asm volatile(
        "mma.sync.aligned.m16n8k16.row.col.f32.bf16.bf16.f32 "
        "{%0,%1,%2,%3}, {%4,%5,%6,%7}, {%8,%9}, {%0,%1,%2,%3};"
        : "+f"(d[0]), "+f"(d[1]), "+f"(d[2]), "+f"(d[3])
        : "r"(a0), "r"(a1), "r"(a2), "r"(a3), "r"(b0), "r"(b1));
}
// fp16 MMA (deform)
__device__ __forceinline__ void mma16816h(float* d, unsigned a0, unsigned a1, unsigned a2, unsigned a3,
                                          unsigned b0, unsigned b1) {
    asm volatile(
        "mma.sync.aligned.m16n8k16.row.col.f32.f16.f16.f32 "
        "{%0,%1,%2,%3}, {%4,%5,%6,%7}, {%8,%9}, {%0,%1,%2,%3};"
        : "+f"(d[0]), "+f"(d[1]), "+f"(d[2]), "+f"(d[3])
        : "r"(a0), "r"(a1), "r"(a2), "r"(a3), "r"(b0), "r"(b1));
}

// ---------------------------------------------------------------------------
// Kernel 0a: deform weight -> fp16 [tap][o][c], XOR-swizzle
// ---------------------------------------------------------------------------
__global__ void wt_prep_kernel(const float* __restrict__ wgt)
{
    int i = blockIdx.x * 256 + threadIdx.x;
    if (i >= 9*64*64) return;
    int c = i & 63, o = (i >> 6) & 63, k = i >> 12;
    float w = wgt[(o*64 + c)*9 + k];
    int off = (o*128 + c*2) ^ ((o & 7) << 4);
    g_wt[k*4096 + (off >> 1)] = __float2half_rn(w);
}

// ---------------------------------------------------------------------------
// Kernel 0b: offset weight [18,64,3,3] -> [tap][24 rows][64 c] bf16 hi/lo
// ---------------------------------------------------------------------------
__global__ void wt2_prep_kernel(const float* __restrict__ ow)
{
    int i = blockIdx.x * 256 + threadIdx.x;
    if (i >= 9*24*64) return;
    int c = i & 63;
    int o = (i >> 6) % 24;
    int k = i / (24*64);
    float w = (o < 18) ? ow[(o*64 + c)*9 + k] : 0.f;
    __nv_bfloat16 hi = __float2bfloat16(w);
    __nv_bfloat16 lo = __float2bfloat16(w - __bfloat162float(hi));
    int off = (o*128 + c*2) ^ ((o & 7) << 4);
    g_ow_hi[k*1536 + (off >> 1)] = hi;
    g_ow_lo[k*1536 + (off >> 1)] = lo;
}

// ---------------------------------------------------------------------------
// Kernel 1: offset conv3x3 via HMMA (bf16, 3-term) — unchanged from R9 pass
// ---------------------------------------------------------------------------
#define PLANE 16640
#define SMO_A_LO (4*PLANE)
#define SMO_B    (8*PLANE)
#define OFFK_SMEM (133120 + 55296)

__global__ void __launch_bounds__(512, 1) offset_mma_kernel(
    const float* __restrict__ x,
    const float* __restrict__ ob)
{
    extern __shared__ char sm[];
    int tid  = threadIdx.x;
    int wid  = tid >> 5;
    int lane = tid & 31;
    int b    = blockIdx.x >> 6;
    int ho0  = (blockIdx.x & 63) << 1;

    unsigned smb = su32(sm);
    unsigned Ahi = smb, Alo = smb + SMO_A_LO;
    unsigned Bhi = smb + SMO_B, Blo = Bhi + 27648;

    for (int off = tid*16; off < 27648; off += 8192) {
        cp_async16(sm + SMO_B         + off, (const char*)g_ow_hi + off);
        cp_async16(sm + SMO_B + 27648 + off, (const char*)g_ow_lo + off);
    }
    CP_COMMIT();

    const float* xb = x + (size_t)b*CC*HWP;
    for (int i = tid; i < 4*32*128; i += 512) {
        int w  = i & 127;
        int cp = (i >> 7) & 31;
        int j  = i >> 12;
        int row = ho0 - 1 + j;
        float v0 = 0.f, v1 = 0.f;
        if ((unsigned)row < (unsigned)HH) {
            v0 = xb[((size_t)(2*cp)  *HH + row)*WW + w];
            v1 = xb[((size_t)(2*cp+1)*HH + row)*WW + w];
        }
        __nv_bfloat162 h2 = __floats2bfloat162_rn(v0, v1);
        float r0 = v0 - __bfloat162float(__low2bfloat16(h2));
        float r1 = v1 - __bfloat162float(__high2bfloat16(h2));
        __nv_bfloat162 l2 = __floats2bfloat162_rn(r0, r1);
        int wp  = w + 1;
        int col = (4*cp) ^ ((wp & 7) << 4);
        int byt = j*PLANE + wp*128 + col;
        *(__nv_bfloat162*)(sm + byt)            = h2;
        *(__nv_bfloat162*)(sm + SMO_A_LO + byt) = l2;
    }
    for (int i = tid; i < 4*2*32; i += 512) {
        int cp = i & 31, e = (i >> 5) & 1, j = i >> 6;
        int wp = e ? 129 : 0;
        int col = (4*cp) ^ ((wp & 7) << 4);
        int byt = j*PLANE + wp*128 + col;
        *(unsigned*)(sm + byt)            = 0u;
        *(unsigned*)(sm + SMO_A_LO + byt) = 0u;
    }
    CP_WAIT0();
    __syncthreads();

    int r  = wid >> 3;
    int pb = (wid & 7) * 16;
    int mr = lane & 7, mm = lane >> 3;
    int p_frag = pb + (mm & 1)*8 + mr;
    unsigned hm = (unsigned)((mm >> 1) * 16);
    unsigned bm = (unsigned)(((lane >> 3) & 1) * 16);

    float acc[12];
    #pragma unroll
    for (int i = 0; i < 12; ++i) acc[i] = 0.f;

    #pragma unroll
    for (int k = 0; k < 9; ++k) {
        int ky = k / 3, kx = k - 3*ky;
        unsigned aPlaneH = Ahi + (unsigned)((r + ky)*PLANE);
        unsigned aPlaneL = Alo + (unsigned)((r + ky)*PLANE);
        int roww = p_frag + kx;
        unsigned arow = (unsigned)(roww*128);
        unsigned sx   = (unsigned)((roww & 7) << 4);
        unsigned bk   = (unsigned)(k*3072);
        #pragma unroll
        for (int kc = 0; kc < 4; ++kc) {
            unsigned la = ((unsigned)(kc*32) + hm) ^ sx;
            unsigned ah0,ah1,ah2,ah3, al0,al1,al2,al3;
            ldsm_x4(ah0,ah1,ah2,ah3, aPlaneH + arow + la);
            ldsm_x4(al0,al1,al2,al3, aPlaneL + arow + la);
            unsigned lb = ((unsigned)(kc*32) + bm) ^ ((unsigned)(mr << 4));
            #pragma unroll
            for (int nt = 0; nt < 3; ++nt) {
                unsigned brow = bk + (unsigned)(nt*1024 + mr*128);
                unsigned bh0, bh1, bl0, bl1;
                ldsm_x2(bh0, bh1, Bhi + brow + lb);
                ldsm_x2(bl0, bl1, Blo + brow + lb);
                mma16816(acc + nt*4, ah0,ah1,ah2,ah3, bh0,bh1);
                mma16816(acc + nt*4, ah0,ah1,ah2,ah3, bl0,bl1);
                mma16816(acc + nt*4, al0,al1,al2,al3, bh0,bh1);
            }
        }
    }

    int g = lane >> 2, tg = lane & 3;
    int how = ho0 + r;
    #pragma unroll
    for (int nt = 0; nt < 3; ++nt) {
        #pragma unroll
        for (int sub = 0; sub < 2; ++sub) {
            int o = nt*8 + tg*2 + sub;
            if (o < NCH) {
                float bv = __ldg(ob + o);
                float* q = g_offset + (((size_t)b*NCH + o)*HH + how)*WW;
                q[pb + g]     = acc[nt*4 + sub]     + bv;
                q[pb + g + 8] = acc[nt*4 + 2 + sub] + bv;
            }
        }
    }
}

// ---------------------------------------------------------------------------
// Kernel 2: deformable conv — single-term fp16 HMMA.
// smem 57KB: val[2 st][128x64 fp16] + wt[2 st][64x64 fp16] + pp
// ---------------------------------------------------------------------------
#define SM_VAL   0        // stage*16384
#define SM_WT    32768    // stage*8192
#define SM_PP    49152    // 9*128*2 floats = 9216 B
#define DEFORM_SMEM (49152 + 9216)

__global__ void __launch_bounds__(512, 2) deform_kernel(
    const float* __restrict__ x,
    const float* __restrict__ bias,
    float* __restrict__ out)
{
    extern __shared__ char sm[];
    float* pp_s = (float*)(sm + SM_PP);

    int tid  = threadIdx.x;
    int wid  = tid >> 5;
    int lane = tid & 31;
    int b    = blockIdx.x >> 7;
    int ho   = blockIdx.x & 127;

    unsigned smb = su32(sm);

    for (int i = tid; i < 9*128; i += 512) {
        int k = i >> 7, p = i & 127;
        int ky = k / 3, kx = k - ky*3;
        const float* offp = g_offset + (((size_t)b*NCH + 2*k)*HH + ho)*WW + p;
        pp_s[i*2+0] = (float)(ho - 1 + ky) + offp[0];
        pp_s[i*2+1] = (float)(p  - 1 + kx) + offp[HWP];
    }

    // prefetch wt tap 0 (8KB = 512 threads x 16B)
    cp_async16(sm + SM_WT + tid*16, (const char*)g_wt + tid*16);
    CP_COMMIT();

    __syncthreads();   // pp_s visible before fill(0)

    int pv = tid & 127;
    int cb = tid >> 7;
    const float* xb = x + (size_t)b*CC*HWP;

    int sA = pv*128 + cb*32;
    int sw0 = sA        ^ ((pv & 7) << 4);
    int sw1 = (sA + 16) ^ ((pv & 7) << 4);

    auto fill = [&](int k, int st) {
        float py = pp_s[(k*128 + pv)*2 + 0];
        float px = pp_s[(k*128 + pv)*2 + 1];
        float fy0 = floorf(py), fx0 = floorf(px);
        int y0 = (int)fy0, x0 = (int)fx0;
        int y1 = y0 + 1,   x1 = x0 + 1;
        float wy1 = py - fy0, wx1 = px - fx0;
        float wy0 = 1.f - wy1, wx0 = 1.f - wx1;
        float vy0 = ((unsigned)y0 < (unsigned)HH) ? 1.f : 0.f;
        float vy1 = ((unsigned)y1 < (unsigned)HH) ? 1.f : 0.f;
        float vx0 = ((unsigned)x0 < (unsigned)WW) ? 1.f : 0.f;
        float vx1 = ((unsigned)x1 < (unsigned)WW) ? 1.f : 0.f;
        int cy0 = min(max(y0,0),HH-1), cy1 = min(max(y1,0),HH-1);
        int cx0 = min(max(x0,0),WW-1), cx1 = min(max(x1,0),WW-1);
        int   i0 = cy0*WW + cx0, i1 = cy0*WW + cx1,
              i2 = cy1*WW + cx0, i3 = cy1*WW + cx1;
        float w0 = wy0*wx0*vy0*vx0, w1 = wy0*wx1*vy0*vx1,
              w2 = wy1*wx0*vy1*vx0, w3 = wy1*wx1*vy1*vx1;

        char* vh = sm + SM_VAL + st*16384;
        const float* xp = xb + (size_t)(cb*16)*HWP;

        #pragma unroll
        for (int h = 0; h < 2; ++h) {
            unsigned hq[4];
            #pragma unroll
            for (int j = 0; j < 4; ++j) {
                const float* pa = xp + (size_t)(h*8 + 2*j)*HWP;
                const float* pb = pa + HWP;
                float v0 = w0*pa[i0] + w1*pa[i1] + w2*pa[i2] + w3*pa[i3];
                float v1 = w0*pb[i0] + w1*pb[i1] + w2*pb[i2] + w3*pb[i3];
                __half2 h2 = __floats2half2_rn(v0, v1);
                hq[j] = reinterpret_cast<unsigned&>(h2);
            }
            int swo = h ? sw1 : sw0;
            *(uint4*)(vh + swo) = make_uint4(hq[0],hq[1],hq[2],hq[3]);
        }
    };

    fill(0, 0);
    CP_WAIT0();
    __syncthreads();

    int mw = wid & 3, nw = wid >> 2;
    int mr = lane & 7, mm = lane >> 3;
    int pixA = mw*32 + (mm & 1)*8 + mr;
    unsigned aRow0 = (unsigned)pixA*128;
    unsigned aRow1 = aRow0 + 16*128;
    unsigned sxa   = (unsigned)((pixA & 7) << 4);
    unsigned hm    = (unsigned)((mm >> 1) * 16);
    int m2 = (lane >> 3) & 1;
    int oR = nw*16 + mr;
    unsigned bRow0 = (unsigned)oR*128;
    unsigned bRow1 = bRow0 + 8*128;
    unsigned sxb   = (unsigned)((oR & 7) << 4);
    unsigned bm    = (unsigned)(m2 * 16);

    float acc[16];
    #pragma unroll
    for (int i = 0; i < 16; ++i) acc[i] = 0.f;

    for (int k = 0; k < 9; ++k) {
        int st = k & 1;
        if (k < 8) {
            int nb = st ^ 1;
            cp_async16(sm + SM_WT + nb*8192 + tid*16,
                       (const char*)g_wt + (k+1)*8192 + tid*16);
            CP_COMMIT();
            fill(k + 1, nb);
        }

        unsigned vh = smb + SM_VAL + st*16384;
        unsigned wh = smb + SM_WT + st*8192;

        #pragma unroll
        for (int kc = 0; kc < 4; ++kc) {
            unsigned la = ((unsigned)(kc*32) + hm) ^ sxa;
            unsigned lb = ((unsigned)(kc*32) + bm) ^ sxb;
            unsigned b0a, b0b, b1a, b1b;
            ldsm_x2(b0a, b0b, wh + bRow0 + lb);
            ldsm_x2(b1a, b1b, wh + bRow1 + lb);
            unsigned a0,a1,a2,a3, c0,c1,c2,c3;
            ldsm_x4(a0,a1,a2,a3, vh + aRow0 + la);
            ldsm_x4(c0,c1,c2,c3, vh + aRow1 + la);
            mma16816h(acc+0,  a0,a1,a2,a3, b0a,b0b);
            mma16816h(acc+4,  a0,a1,a2,a3, b1a,b1b);
            mma16816h(acc+8,  c0,c1,c2,c3, b0a,b0b);
            mma16816h(acc+12, c0,c1,c2,c3, b1a,b1b);
        }

        if (k < 8) CP_WAIT0();
        __syncthreads();
    }

    int g  = lane >> 2, tg = lane & 3;
    float* ob = out + (size_t)b*OO*HWP + (size_t)ho*WW;
    #pragma unroll
    for (int mi = 0; mi < 2; ++mi) {
        #pragma unroll
        for (int ni = 0; ni < 2; ++ni) {
            int p0 = mw*32 + mi*16 + g;
            int o0 = nw*16 + ni*8 + tg*2;
            float bv0 = __ldg(bias + o0), bv1 = __ldg(bias + o0 + 1);
            float* q0 = ob + (size_t)o0*HWP;
            float* q1 = q0 + HWP;
            const float* a = acc + (mi*2 + ni)*4;
            q0[p0]     = a[0] + bv0;
            q1[p0]     = a[1] + bv1;
            q0[p0 + 8] = a[2] + bv0;
            q1[p0 + 8] = a[3] + bv1;
        }
    }
}

extern "C" void kernel_launch(void* const* d_in, const int* in_sizes, int n_in,
                              void* d_out, int out_size)
{
    const float* x    = (const float*)d_in[0];
    const float* ow   = (const float*)d_in[1];
    const float* ob   = (const float*)d_in[2];
    const float* wgt  = (const float*)d_in[3];
    const float* bias = (const float*)d_in[4];
    float* out = (float*)d_out;

    cudaFuncSetAttribute(deform_kernel,
                         cudaFuncAttributeMaxDynamicSharedMemorySize, DEFORM_SMEM);
    cudaFuncSetAttribute(offset_mma_kernel,
                         cudaFuncAttributeMaxDynamicSharedMemorySize, OFFK_SMEM);

    wt_prep_kernel<<<(9*64*64 + 255)/256, 256>>>(wgt);
    wt2_prep_kernel<<<(9*24*64 + 255)/256, 256>>>(ow);
    offset_mma_kernel<<<BB*64, 512, OFFK_SMEM>>>(x, ob);
    deform_kernel<<<BB*HH, 512, DEFORM_SMEM>>>(x, bias, out);
}

// round 13
// speedup vs baseline: 4.6763x; 1.0377x over previous
#include <cuda_runtime.h>
#include <cuda_bf16.h>
#include <cuda_fp16.h>
#include <cstdint>

#define HH 128
#define WW 128
#define HWP (HH*WW)
#define CC 64
#define OO 64
#define BB 4
#define NCH 18

// scratch
__device__ float g_offset[BB*NCH*HH*WW];
// deform weights per tap: 64 o-rows x 128B (64 fp16 ch), XOR-swizzled within row
__device__ __half g_wt[9*4096];
// offset-conv weights per tap: 24 o-rows (18 real + 6 zero) x 128B, swizzled (bf16 hi/lo)
__device__ __nv_bfloat16 g_ow_hi[9*24*64];
__device__ __nv_bfloat16 g_ow_lo[9*24*64];

// ---------------- helpers ----------------
__device__ __forceinline__ void cp_async16(void* smem, const void* gmem) {
    unsigned saddr = (unsigned)__cvta_generic_to_shared(smem);
    asm volatile("cp.async.cg.shared.global [%0], [%1], 16;\n" :: "r"(saddr), "l"(gmem));
}
#define CP_COMMIT() asm volatile("cp.async.commit_group;\n" ::: "memory")
#define CP_WAIT0()  asm volatile("cp.async.wait_group 0;\n" ::: "memory")

__device__ __forceinline__ unsigned su32(const void* p) {
    unsigned a;
    asm("{ .reg .u64 t; cvta.to.shared.u64 t, %1; cvt.u32.u64 %0, t; }" : "=r"(a) : "l"(p));
    return a;
}
__device__ __forceinline__ void ldsm_x4(unsigned& r0, unsigned& r1, unsigned& r2, unsigned& r3, unsigned a) {
    asm volatile("ldmatrix.sync.aligned.m8n8.x4.shared.b16 {%0,%1,%2,%3}, [%4];"
                 : "=r"(r0), "=r"(r1), "=r"(r2), "=r"(r3) : "r"(a));
}
__device__ __forceinline__ void ldsm_x2(unsigned& r0, unsigned& r1, unsigned a) {
    asm volatile("ldmatrix.sync.aligned.m8n8.x2.shared.b16 {%0,%1}, [%2];"
                 : "=r"(r0), "=r"(r1) : "r"(a));
}
// bf16 MMA (offset conv)
__device__ __forceinline__ void mma16816(float* d, unsigned a0, unsigned a1, unsigned a2, unsigned a3,
                                         unsigned b0, unsigned b1) {
    asm volatile(
        "mma.sync.aligned.m16n8k16.row.col.f32.bf16.bf16.f32 "
        "{%0,%1,%2,%3}, {%4,%5,%6,%7}, {%8,%9}, {%0,%1,%2,%3};"
        : "+f"(d[0]), "+f"(d[1]), "+f"(d[2]), "+f"(d[3])
        : "r"(a0), "r"(a1), "r"(a2), "r"(a3), "r"(b0), "r"(b1));
}
// fp16 MMA (deform)
__device__ __forceinline__ void mma16816h(float* d, unsigned a0, unsigned a1, unsigned a2, unsigned a3,
                                          unsigned b0, unsigned b1) {
    asm volatile(
        "mma.sync.aligned.m16n8k16.row.col.f32.f16.f16.f32 "
        "{%0,%1,%2,%3}, {%4,%5,%6,%7}, {%8,%9}, {%0,%1,%2,%3};"
        : "+f"(d[0]), "+f"(d[1]), "+f"(d[2]), "+f"(d[3])
        : "r"(a0), "r"(a1), "r"(a2), "r"(a3), "r"(b0), "r"(b1));
}

// ---------------------------------------------------------------------------
// Kernel 0: fused weight prep.
//   i < 9*4096             : deform weight -> fp16 [tap][o][c], swizzled
//   i >= 9*4096 (9*1536)   : offset weight -> bf16 hi/lo [tap][24][c], swizzled
// ---------------------------------------------------------------------------
#define NW1 (9*4096)
#define NW2 (9*1536)
__global__ void wt_prep_fused(const float* __restrict__ wgt,
                              const float* __restrict__ ow)
{
    int i = blockIdx.x * 256 + threadIdx.x;
    if (i < NW1) {
        int c = i & 63, o = (i >> 6) & 63, k = i >> 12;
        float w = wgt[(o*64 + c)*9 + k];
        int off = (o*128 + c*2) ^ ((o & 7) << 4);
        g_wt[k*4096 + (off >> 1)] = __float2half_rn(w);
    } else if (i < NW1 + NW2) {
        int j = i - NW1;
        int c = j & 63;
        int o = (j >> 6) % 24;
        int k = j / (24*64);
        float w = (o < 18) ? ow[(o*64 + c)*9 + k] : 0.f;
        __nv_bfloat16 hi = __float2bfloat16(w);
        __nv_bfloat16 lo = __float2bfloat16(w - __bfloat162float(hi));
        int off = (o*128 + c*2) ^ ((o & 7) << 4);
        g_ow_hi[k*1536 + (off >> 1)] = hi;
        g_ow_lo[k*1536 + (off >> 1)] = lo;
    }
}

// ---------------------------------------------------------------------------
// Kernel 1: offset conv3x3 via HMMA (bf16, 3-term) — unchanged (proven)
// ---------------------------------------------------------------------------
#define PLANE 16640
#define SMO_A_LO (4*PLANE)
#define SMO_B    (8*PLANE)
#define OFFK_SMEM (133120 + 55296)

__global__ void __launch_bounds__(512, 1) offset_mma_kernel(
    const float* __restrict__ x,
    const float* __restrict__ ob)
{
    extern __shared__ char sm[];
    int tid  = threadIdx.x;
    int wid  = tid >> 5;
    int lane = tid & 31;
    int b    = blockIdx.x >> 6;
    int ho0  = (blockIdx.x & 63) << 1;

    unsigned smb = su32(sm);
    unsigned Ahi = smb, Alo = smb + SMO_A_LO;
    unsigned Bhi = smb + SMO_B, Blo = Bhi + 27648;

    for (int off = tid*16; off < 27648; off += 8192) {
        cp_async16(sm + SMO_B         + off, (const char*)g_ow_hi + off);
        cp_async16(sm + SMO_B + 27648 + off, (const char*)g_ow_lo + off);
    }
    CP_COMMIT();

    const float* xb = x + (size_t)b*CC*HWP;
    for (int i = tid; i < 4*32*128; i += 512) {
        int w  = i & 127;
        int cp = (i >> 7) & 31;
        int j  = i >> 12;
        int row = ho0 - 1 + j;
        float v0 = 0.f, v1 = 0.f;
        if ((unsigned)row < (unsigned)HH) {
            v0 = xb[((size_t)(2*cp)  *HH + row)*WW + w];
            v1 = xb[((size_t)(2*cp+1)*HH + row)*WW + w];
        }
        __nv_bfloat162 h2 = __floats2bfloat162_rn(v0, v1);
        float r0 = v0 - __bfloat162float(__low2bfloat16(h2));
        float r1 = v1 - __bfloat162float(__high2bfloat16(h2));
        __nv_bfloat162 l2 = __floats2bfloat162_rn(r0, r1);
        int wp  = w + 1;
        int col = (4*cp) ^ ((wp & 7) << 4);
        int byt = j*PLANE + wp*128 + col;
        *(__nv_bfloat162*)(sm + byt)            = h2;
        *(__nv_bfloat162*)(sm + SMO_A_LO + byt) = l2;
    }
    for (int i = tid; i < 4*2*32; i += 512) {
        int cp = i & 31, e = (i >> 5) & 1, j = i >> 6;
        int wp = e ? 129 : 0;
        int col = (4*cp) ^ ((wp & 7) << 4);
        int byt = j*PLANE + wp*128 + col;
        *(unsigned*)(sm + byt)            = 0u;
        *(unsigned*)(sm + SMO_A_LO + byt) = 0u;
    }
    CP_WAIT0();
    __syncthreads();

    int r  = wid >> 3;
    int pb = (wid & 7) * 16;
    int mr = lane & 7, mm = lane >> 3;
    int p_frag = pb + (mm & 1)*8 + mr;
    unsigned hm = (unsigned)((mm >> 1) * 16);
    unsigned bm = (unsigned)(((lane >> 3) & 1) * 16);

    float acc[12];
    #pragma unroll
    for (int i = 0; i < 12; ++i) acc[i] = 0.f;

    #pragma unroll
    for (int k = 0; k < 9; ++k) {
        int ky = k / 3, kx = k - 3*ky;
        unsigned aPlaneH = Ahi + (unsigned)((r + ky)*PLANE);
        unsigned aPlaneL = Alo + (unsigned)((r + ky)*PLANE);
        int roww = p_frag + kx;
        unsigned arow = (unsigned)(roww*128);
        unsigned sx   = (unsigned)((roww & 7) << 4);
        unsigned bk   = (unsigned)(k*3072);
        #pragma unroll
        for (int kc = 0; kc < 4; ++kc) {
            unsigned la = ((unsigned)(kc*32) + hm) ^ sx;
            unsigned ah0,ah1,ah2,ah3, al0,al1,al2,al3;
            ldsm_x4(ah0,ah1,ah2,ah3, aPlaneH + arow + la);
            ldsm_x4(al0,al1,al2,al3, aPlaneL + arow + la);
            unsigned lb = ((unsigned)(kc*32) + bm) ^ ((unsigned)(mr << 4));
            #pragma unroll
            for (int nt = 0; nt < 3; ++nt) {
                unsigned brow = bk + (unsigned)(nt*1024 + mr*128);
                unsigned bh0, bh1, bl0, bl1;
                ldsm_x2(bh0, bh1, Bhi + brow + lb);
                ldsm_x2(bl0, bl1, Blo + brow + lb);
                mma16816(acc + nt*4, ah0,ah1,ah2,ah3, bh0,bh1);
                mma16816(acc + nt*4, ah0,ah1,ah2,ah3, bl0,bl1);
                mma16816(acc + nt*4, al0,al1,al2,al3, bh0,bh1);
            }
        }
    }

    int g = lane >> 2, tg = lane & 3;
    int how = ho0 + r;
    #pragma unroll
    for (int nt = 0; nt < 3; ++nt) {
        #pragma unroll
        for (int sub = 0; sub < 2; ++sub) {
            int o = nt*8 + tg*2 + sub;
            if (o < NCH) {
                float bv = __ldg(ob + o);
                float* q = g_offset + (((size_t)b*NCH + o)*HH + how)*WW;
                q[pb + g]     = acc[nt*4 + sub]     + bv;
                q[pb + g + 8] = acc[nt*4 + 2 + sub] + bv;
            }
        }
    }
}

// ---------------------------------------------------------------------------
// Kernel 2: deformable conv — single-term fp16 HMMA, HALF-ROW CTAs.
// Block = 64 px (half of one (b,ho) row), 256 threads (8 warps), 4 CTAs/SM.
// smem 37KB: val[2 st][64x64 fp16] + wt[2 st][64x64 fp16] + pp[9][64][2]
// Warp tiles: 2 m-warps (32 px) x 4 n-warps (16 o).
// ---------------------------------------------------------------------------
#define SM_VAL   0        // stage*8192
#define SM_WT    16384    // stage*8192
#define SM_PP    32768    // 9*64*2 floats = 4608 B
#define DEFORM_SMEM (32768 + 4608)

__global__ void __launch_bounds__(256, 4) deform_kernel(
    const float* __restrict__ x,
    const float* __restrict__ bias,
    float* __restrict__ out)
{
    extern __shared__ char sm[];
    float* pp_s = (float*)(sm + SM_PP);

    int tid   = threadIdx.x;
    int wid   = tid >> 5;
    int lane  = tid & 31;
    int blk   = blockIdx.x;
    int b     = blk >> 8;
    int ho    = (blk >> 1) & 127;
    int pbase = (blk & 1) << 6;   // 0 or 64

    unsigned smb = su32(sm);

    // stage sampling positions for 9 taps x 64 px
    for (int i = tid; i < 9*64; i += 256) {
        int k = i >> 6, p = i & 63;
        int gp = pbase + p;
        int ky = k / 3, kx = k - ky*3;
        const float* offp = g_offset + (((size_t)b*NCH + 2*k)*HH + ho)*WW + gp;
        pp_s[i*2+0] = (float)(ho - 1 + ky) + offp[0];
        pp_s[i*2+1] = (float)(gp - 1 + kx) + offp[HWP];
    }

    // prefetch wt tap 0 (8KB = 256 threads x 2 x 16B)
    cp_async16(sm + SM_WT        + tid*16, (const char*)g_wt        + tid*16);
    cp_async16(sm + SM_WT + 4096 + tid*16, (const char*)g_wt + 4096 + tid*16);
    CP_COMMIT();

    __syncthreads();   // pp_s visible before fill(0)

    int pv = tid & 63;    // pixel within half-row
    int cb = tid >> 6;    // channel block 0..3
    const float* xb = x + (size_t)b*CC*HWP;

    int sA = pv*128 + cb*32;
    int sw0 = sA        ^ ((pv & 7) << 4);
    int sw1 = (sA + 16) ^ ((pv & 7) << 4);

    auto fill = [&](int k, int st) {
        float py = pp_s[(k*64 + pv)*2 + 0];
        float px = pp_s[(k*64 + pv)*2 + 1];
        float fy0 = floorf(py), fx0 = floorf(px);
        int y0 = (int)fy0, x0 = (int)fx0;
        int y1 = y0 + 1,   x1 = x0 + 1;
        float wy1 = py - fy0, wx1 = px - fx0;
        float wy0 = 1.f - wy1, wx0 = 1.f - wx1;
        float vy0 = ((unsigned)y0 < (unsigned)HH) ? 1.f : 0.f;
        float vy1 = ((unsigned)y1 < (unsigned)HH) ? 1.f : 0.f;
        float vx0 = ((unsigned)x0 < (unsigned)WW) ? 1.f : 0.f;
        float vx1 = ((unsigned)x1 < (unsigned)WW) ? 1.f : 0.f;
        int cy0 = min(max(y0,0),HH-1), cy1 = min(max(y1,0),HH-1);
        int cx0 = min(max(x0,0),WW-1), cx1 = min(max(x1,0),WW-1);
        int   i0 = cy0*WW + cx0, i1 = cy0*WW + cx1,
              i2 = cy1*WW + cx0, i3 = cy1*WW + cx1;
        float w0 = wy0*wx0*vy0*vx0, w1 = wy0*wx1*vy0*vx1,
              w2 = wy1*wx0*vy1*vx0, w3 = wy1*wx1*vy1*vx1;

        char* vh = sm + SM_VAL + st*8192;
        const float* xp = xb + (size_t)(cb*16)*HWP;

        #pragma unroll
        for (int h = 0; h < 2; ++h) {
            unsigned hq[4];
            #pragma unroll
            for (int j = 0; j < 4; ++j) {
                const float* pa = xp + (size_t)(h*8 + 2*j)*HWP;
                const float* pb = pa + HWP;
                float v0 = w0*pa[i0] + w1*pa[i1] + w2*pa[i2] + w3*pa[i3];
                float v1 = w0*pb[i0] + w1*pb[i1] + w2*pb[i2] + w3*pb[i3];
                __half2 h2 = __floats2half2_rn(v0, v1);
                hq[j] = reinterpret_cast<unsigned&>(h2);
            }
            int swo = h ? sw1 : sw0;
            *(uint4*)(vh + swo) = make_uint4(hq[0],hq[1],hq[2],hq[3]);
        }
    };

    fill(0, 0);
    CP_WAIT0();
    __syncthreads();

    // warp tiles: mw in {0,1} (32 px), nw in {0..3} (16 o)
    int mw = wid & 1, nw = wid >> 1;
    int mr = lane & 7, mm = lane >> 3;
    int pixA = mw*32 + (mm & 1)*8 + mr;
    unsigned aRow0 = (unsigned)pixA*128;
    unsigned aRow1 = aRow0 + 16*128;
    unsigned sxa   = (unsigned)((pixA & 7) << 4);
    unsigned hm    = (unsigned)((mm >> 1) * 16);
    int m2 = (lane >> 3) & 1;
    int oR = nw*16 + mr;
    unsigned bRow0 = (unsigned)oR*128;
    unsigned bRow1 = bRow0 + 8*128;
    unsigned sxb   = (unsigned)((oR & 7) << 4);
    unsigned bm    = (unsigned)(m2 * 16);

    float acc[16];
    #pragma unroll
    for (int i = 0; i < 16; ++i) acc[i] = 0.f;

    for (int k = 0; k < 9; ++k) {
        int st = k & 1;
        if (k < 8) {
            int nb = st ^ 1;
            const char* src = (const char*)g_wt + (k+1)*8192;
            cp_async16(sm + SM_WT + nb*8192        + tid*16, src        + tid*16);
            cp_async16(sm + SM_WT + nb*8192 + 4096 + tid*16, src + 4096 + tid*16);
            CP_COMMIT();
            fill(k + 1, nb);
        }

        unsigned vh = smb + SM_VAL + st*8192;
        unsigned wh = smb + SM_WT  + st*8192;

        #pragma unroll
        for (int kc = 0; kc < 4; ++kc) {
            unsigned la = ((unsigned)(kc*32) + hm) ^ sxa;
            unsigned lb = ((unsigned)(kc*32) + bm) ^ sxb;
            unsigned b0a, b0b, b1a, b1b;
            ldsm_x2(b0a, b0b, wh + bRow0 + lb);
            ldsm_x2(b1a, b1b, wh + bRow1 + lb);
            unsigned a0,a1,a2,a3, c0,c1,c2,c3;
            ldsm_x4(a0,a1,a2,a3, vh + aRow0 + la);
            ldsm_x4(c0,c1,c2,c3, vh + aRow1 + la);
            mma16816h(acc+0,  a0,a1,a2,a3, b0a,b0b);
            mma16816h(acc+4,  a0,a1,a2,a3, b1a,b1b);
            mma16816h(acc+8,  c0,c1,c2,c3, b0a,b0b);
            mma16816h(acc+12, c0,c1,c2,c3, b1a,b1b);
        }

        if (k < 8) CP_WAIT0();
        __syncthreads();
    }

    int g  = lane >> 2, tg = lane & 3;
    float* ob = out + (size_t)b*OO*HWP + (size_t)ho*WW + pbase;
    #pragma unroll
    for (int mi = 0; mi < 2; ++mi) {
        #pragma unroll
        for (int ni = 0; ni < 2; ++ni) {
            int p0 = mw*32 + mi*16 + g;
            int o0 = nw*16 + ni*8 + tg*2;
            float bv0 = __ldg(bias + o0), bv1 = __ldg(bias + o0 + 1);
            float* q0 = ob + (size_t)o0*HWP;
            float* q1 = q0 + HWP;
            const float* a = acc + (mi*2 + ni)*4;
            q0[p0]     = a[0] + bv0;
            q1[p0]     = a[1] + bv1;
            q0[p0 + 8] = a[2] + bv0;
            q1[p0 + 8] = a[3] + bv1;
        }
    }
}

extern "C" void kernel_launch(void* const* d_in, const int* in_sizes, int n_in,
                              void* d_out, int out_size)
{
    const float* x    = (const float*)d_in[0];
    const float* ow   = (const float*)d_in[1];
    const float* ob   = (const float*)d_in[2];
    const float* wgt  = (const float*)d_in[3];
    const float* bias = (const float*)d_in[4];
    float* out = (float*)d_out;

    cudaFuncSetAttribute(deform_kernel,
                         cudaFuncAttributeMaxDynamicSharedMemorySize, DEFORM_SMEM);
    cudaFuncSetAttribute(offset_mma_kernel,
                         cudaFuncAttributeMaxDynamicSharedMemorySize, OFFK_SMEM);

    wt_prep_fused<<<(NW1 + NW2 + 255)/256, 256>>>(wgt, ow);
    offset_mma_kernel<<<BB*64, 512, OFFK_SMEM>>>(x, ob);
    deform_kernel<<<BB*HH*2, 256, DEFORM_SMEM>>>(x, bias, out);
}

// round 14
// speedup vs baseline: 4.8679x; 1.0410x over previous
#include <cuda_runtime.h>
#include <cuda_bf16.h>
#include <cuda_fp16.h>
#include <cstdint>

#define HH 128
#define WW 128
#define HWP (HH*WW)
#define CC 64
#define OO 64
#define BB 4
#define NCH 18

// scratch
__device__ float g_offset[BB*NCH*HH*WW];
__device__ __half g_xh[BB*CC*HWP];          // fp16 copy of x for gathers
// deform weights per tap: 64 o-rows x 128B (64 fp16 ch), XOR-swizzled within row
__device__ __half g_wt[9*4096];
// offset-conv weights per tap: 24 o-rows (18 real + 6 zero) x 128B, swizzled (bf16 hi/lo)
__device__ __nv_bfloat16 g_ow_hi[9*24*64];
__device__ __nv_bfloat16 g_ow_lo[9*24*64];

// ---------------- helpers ----------------
__device__ __forceinline__ void cp_async16(void* smem, const void* gmem) {
    unsigned saddr = (unsigned)__cvta_generic_to_shared(smem);
    asm volatile("cp.async.cg.shared.global [%0], [%1], 16;\n" :: "r"(saddr), "l"(gmem));
}
#define CP_COMMIT() asm volatile("cp.async.commit_group;\n" ::: "memory")
#define CP_WAIT0()  asm volatile("cp.async.wait_group 0;\n" ::: "memory")

__device__ __forceinline__ unsigned su32(const void* p) {
    unsigned a;
    asm("{ .reg .u64 t; cvta.to.shared.u64 t, %1; cvt.u32.u64 %0, t; }" : "=r"(a) : "l"(p));
    return a;
}
__device__ __forceinline__ void ldsm_x4(unsigned& r0, unsigned& r1, unsigned& r2, unsigned& r3, unsigned a) {
    asm volatile("ldmatrix.sync.aligned.m8n8.x4.shared.b16 {%0,%1,%2,%3}, [%4];"
                 : "=r"(r0), "=r"(r1), "=r"(r2), "=r"(r3) : "r"(a));
}
__device__ __forceinline__ void ldsm_x2(unsigned& r0, unsigned& r1, unsigned a) {
    asm volatile("ldmatrix.sync.aligned.m8n8.x2.shared.b16 {%0,%1}, [%2];"
                 : "=r"(r0), "=r"(r1) : "r"(a));
}
// bf16 MMA (offset conv)
__device__ __forceinline__ void mma16816(float* d, unsigned a0, unsigned a1, unsigned a2, unsigned a3,
                                         unsigned b0, unsigned b1) {
    asm volatile(
        "mma.sync.aligned.m16n8k16.row.col.f32.bf16.bf16.f32 "
        "{%0,%1,%2,%3}, {%4,%5,%6,%7}, {%8,%9}, {%0,%1,%2,%3};"
        : "+f"(d[0]), "+f"(d[1]), "+f"(d[2]), "+f"(d[3])
        : "r"(a0), "r"(a1), "r"(a2), "r"(a3), "r"(b0), "r"(b1));
}
// fp16 MMA (deform)
__device__ __forceinline__ void mma16816h(float* d, unsigned a0, unsigned a1, unsigned a2, unsigned a3,
                                          unsigned b0, unsigned b1) {
    asm volatile(
        "mma.sync.aligned.m16n8k16.row.col.f32.f16.f16.f32 "
        "{%0,%1,%2,%3}, {%4,%5,%6,%7}, {%8,%9}, {%0,%1,%2,%3};"
        : "+f"(d[0]), "+f"(d[1]), "+f"(d[2]), "+f"(d[3])
        : "r"(a0), "r"(a1), "r"(a2), "r"(a3), "r"(b0), "r"(b1));
}

// ---------------------------------------------------------------------------
// Kernel 0a: x -> fp16 copy (vectorized: float4 in, half2x2 out)
// ---------------------------------------------------------------------------
__global__ void x2h_kernel(const float* __restrict__ x)
{
    int i = (blockIdx.x * 256 + threadIdx.x) * 4;
    float4 v = *(const float4*)(x + i);
    __half2 lo = __floats2half2_rn(v.x, v.y);
    __half2 hi = __floats2half2_rn(v.z, v.w);
    *(__half2*)(g_xh + i)     = lo;
    *(__half2*)(g_xh + i + 2) = hi;
}

// ---------------------------------------------------------------------------
// Kernel 0b: fused weight prep (deform fp16 + offset bf16 hi/lo)
// ---------------------------------------------------------------------------
#define NW1 (9*4096)
#define NW2 (9*1536)
__global__ void wt_prep_fused(const float* __restrict__ wgt,
                              const float* __restrict__ ow)
{
    int i = blockIdx.x * 256 + threadIdx.x;
    if (i < NW1) {
        int c = i & 63, o = (i >> 6) & 63, k = i >> 12;
        float w = wgt[(o*64 + c)*9 + k];
        int off = (o*128 + c*2) ^ ((o & 7) << 4);
        g_wt[k*4096 + (off >> 1)] = __float2half_rn(w);
    } else if (i < NW1 + NW2) {
        int j = i - NW1;
        int c = j & 63;
        int o = (j >> 6) % 24;
        int k = j / (24*64);
        float w = (o < 18) ? ow[(o*64 + c)*9 + k] : 0.f;
        __nv_bfloat16 hi = __float2bfloat16(w);
        __nv_bfloat16 lo = __float2bfloat16(w - __bfloat162float(hi));
        int off = (o*128 + c*2) ^ ((o & 7) << 4);
        g_ow_hi[k*1536 + (off >> 1)] = hi;
        g_ow_lo[k*1536 + (off >> 1)] = lo;
    }
}

// ---------------------------------------------------------------------------
// Kernel 1: offset conv3x3 via HMMA (bf16, 3-term) — unchanged (proven)
// ---------------------------------------------------------------------------
#define PLANE 16640
#define SMO_A_LO (4*PLANE)
#define SMO_B    (8*PLANE)
#define OFFK_SMEM (133120 + 55296)

__global__ void __launch_bounds__(512, 1) offset_mma_kernel(
    const float* __restrict__ x,
    const float* __restrict__ ob)
{
    extern __shared__ char sm[];
    int tid  = threadIdx.x;
    int wid  = tid >> 5;
    int lane = tid & 31;
    int b    = blockIdx.x >> 6;
    int ho0  = (blockIdx.x & 63) << 1;

    unsigned smb = su32(sm);
    unsigned Ahi = smb, Alo = smb + SMO_A_LO;
    unsigned Bhi = smb + SMO_B, Blo = Bhi + 27648;

    for (int off = tid*16; off < 27648; off += 8192) {
        cp_async16(sm + SMO_B         + off, (const char*)g_ow_hi + off);
        cp_async16(sm + SMO_B + 27648 + off, (const char*)g_ow_lo + off);
    }
    CP_COMMIT();

    const float* xb = x + (size_t)b*CC*HWP;
    for (int i = tid; i < 4*32*128; i += 512) {
        int w  = i & 127;
        int cp = (i >> 7) & 31;
        int j  = i >> 12;
        int row = ho0 - 1 + j;
        float v0 = 0.f, v1 = 0.f;
        if ((unsigned)row < (unsigned)HH) {
            v0 = xb[((size_t)(2*cp)  *HH + row)*WW + w];
            v1 = xb[((size_t)(2*cp+1)*HH + row)*WW + w];
        }
        __nv_bfloat162 h2 = __floats2bfloat162_rn(v0, v1);
        float r0 = v0 - __bfloat162float(__low2bfloat16(h2));
        float r1 = v1 - __bfloat162float(__high2bfloat16(h2));
        __nv_bfloat162 l2 = __floats2bfloat162_rn(r0, r1);
        int wp  = w + 1;
        int col = (4*cp) ^ ((wp & 7) << 4);
        int byt = j*PLANE + wp*128 + col;
        *(__nv_bfloat162*)(sm + byt)            = h2;
        *(__nv_bfloat162*)(sm + SMO_A_LO + byt) = l2;
    }
    for (int i = tid; i < 4*2*32; i += 512) {
        int cp = i & 31, e = (i >> 5) & 1, j = i >> 6;
        int wp = e ? 129 : 0;
        int col = (4*cp) ^ ((wp & 7) << 4);
        int byt = j*PLANE + wp*128 + col;
        *(unsigned*)(sm + byt)            = 0u;
        *(unsigned*)(sm + SMO_A_LO + byt) = 0u;
    }
    CP_WAIT0();
    __syncthreads();

    int r  = wid >> 3;
    int pb = (wid & 7) * 16;
    int mr = lane & 7, mm = lane >> 3;
    int p_frag = pb + (mm & 1)*8 + mr;
    unsigned hm = (unsigned)((mm >> 1) * 16);
    unsigned bm = (unsigned)(((lane >> 3) & 1) * 16);

    float acc[12];
    #pragma unroll
    for (int i = 0; i < 12; ++i) acc[i] = 0.f;

    #pragma unroll
    for (int k = 0; k < 9; ++k) {
        int ky = k / 3, kx = k - 3*ky;
        unsigned aPlaneH = Ahi + (unsigned)((r + ky)*PLANE);
        unsigned aPlaneL = Alo + (unsigned)((r + ky)*PLANE);
        int roww = p_frag + kx;
        unsigned arow = (unsigned)(roww*128);
        unsigned sx   = (unsigned)((roww & 7) << 4);
        unsigned bk   = (unsigned)(k*3072);
        #pragma unroll
        for (int kc = 0; kc < 4; ++kc) {
            unsigned la = ((unsigned)(kc*32) + hm) ^ sx;
            unsigned ah0,ah1,ah2,ah3, al0,al1,al2,al3;
            ldsm_x4(ah0,ah1,ah2,ah3, aPlaneH + arow + la);
            ldsm_x4(al0,al1,al2,al3, aPlaneL + arow + la);
            unsigned lb = ((unsigned)(kc*32) + bm) ^ ((unsigned)(mr << 4));
            #pragma unroll
            for (int nt = 0; nt < 3; ++nt) {
                unsigned brow = bk + (unsigned)(nt*1024 + mr*128);
                unsigned bh0, bh1, bl0, bl1;
                ldsm_x2(bh0, bh1, Bhi + brow + lb);
                ldsm_x2(bl0, bl1, Blo + brow + lb);
                mma16816(acc + nt*4, ah0,ah1,ah2,ah3, bh0,bh1);
                mma16816(acc + nt*4, ah0,ah1,ah2,ah3, bl0,bl1);
                mma16816(acc + nt*4, al0,al1,al2,al3, bh0,bh1);
            }
        }
    }

    int g = lane >> 2, tg = lane & 3;
    int how = ho0 + r;
    #pragma unroll
    for (int nt = 0; nt < 3; ++nt) {
        #pragma unroll
        for (int sub = 0; sub < 2; ++sub) {
            int o = nt*8 + tg*2 + sub;
            if (o < NCH) {
                float bv = __ldg(ob + o);
                float* q = g_offset + (((size_t)b*NCH + o)*HH + how)*WW;
                q[pb + g]     = acc[nt*4 + sub]     + bv;
                q[pb + g + 8] = acc[nt*4 + 2 + sub] + bv;
            }
        }
    }
}

// ---------------------------------------------------------------------------
// Kernel 2: deformable conv — fp16 HMMA, half-row CTAs, fp16 gathers.
// ---------------------------------------------------------------------------
#define SM_VAL   0        // stage*8192
#define SM_WT    16384    // stage*8192
#define SM_PP    32768    // 9*64*2 floats = 4608 B
#define DEFORM_SMEM (32768 + 4608)

__global__ void __launch_bounds__(256, 4) deform_kernel(
    const float* __restrict__ bias,
    float* __restrict__ out)
{
    extern __shared__ char sm[];
    float* pp_s = (float*)(sm + SM_PP);

    int tid   = threadIdx.x;
    int wid   = tid >> 5;
    int lane  = tid & 31;
    int blk   = blockIdx.x;
    int b     = blk >> 8;
    int ho    = (blk >> 1) & 127;
    int pbase = (blk & 1) << 6;   // 0 or 64

    unsigned smb = su32(sm);

    // stage sampling positions for 9 taps x 64 px
    for (int i = tid; i < 9*64; i += 256) {
        int k = i >> 6, p = i & 63;
        int gp = pbase + p;
        int ky = k / 3, kx = k - ky*3;
        const float* offp = g_offset + (((size_t)b*NCH + 2*k)*HH + ho)*WW + gp;
        pp_s[i*2+0] = (float)(ho - 1 + ky) + offp[0];
        pp_s[i*2+1] = (float)(gp - 1 + kx) + offp[HWP];
    }

    // prefetch wt tap 0 (8KB = 256 threads x 2 x 16B)
    cp_async16(sm + SM_WT        + tid*16, (const char*)g_wt        + tid*16);
    cp_async16(sm + SM_WT + 4096 + tid*16, (const char*)g_wt + 4096 + tid*16);
    CP_COMMIT();

    __syncthreads();   // pp_s visible before fill(0)

    int pv = tid & 63;    // pixel within half-row
    int cb = tid >> 6;    // channel block 0..3
    const __half* xb = g_xh + (size_t)b*CC*HWP;

    int sA = pv*128 + cb*32;
    int sw0 = sA        ^ ((pv & 7) << 4);
    int sw1 = (sA + 16) ^ ((pv & 7) << 4);

    auto fill = [&](int k, int st) {
        float py = pp_s[(k*64 + pv)*2 + 0];
        float px = pp_s[(k*64 + pv)*2 + 1];
        float fy0 = floorf(py), fx0 = floorf(px);
        int y0 = (int)fy0, x0 = (int)fx0;
        int y1 = y0 + 1,   x1 = x0 + 1;
        float wy1 = py - fy0, wx1 = px - fx0;
        float wy0 = 1.f - wy1, wx0 = 1.f - wx1;
        float vy0 = ((unsigned)y0 < (unsigned)HH) ? 1.f : 0.f;
        float vy1 = ((unsigned)y1 < (unsigned)HH) ? 1.f : 0.f;
        float vx0 = ((unsigned)x0 < (unsigned)WW) ? 1.f : 0.f;
        float vx1 = ((unsigned)x1 < (unsigned)WW) ? 1.f : 0.f;
        int cy0 = min(max(y0,0),HH-1), cy1 = min(max(y1,0),HH-1);
        int cx0 = min(max(x0,0),WW-1), cx1 = min(max(x1,0),WW-1);
        int   i0 = cy0*WW + cx0, i1 = cy0*WW + cx1,
              i2 = cy1*WW + cx0, i3 = cy1*WW + cx1;
        float w0 = wy0*wx0*vy0*vx0, w1 = wy0*wx1*vy0*vx1,
              w2 = wy1*wx0*vy1*vx0, w3 = wy1*wx1*vy1*vx1;

        char* vh = sm + SM_VAL + st*8192;
        const __half* xp = xb + (size_t)(cb*16)*HWP;

        #pragma unroll
        for (int h = 0; h < 2; ++h) {
            unsigned hq[4];
            #pragma unroll
            for (int j = 0; j < 4; ++j) {
                const __half* pa = xp + (size_t)(h*8 + 2*j)*HWP;
                const __half* pb = pa + HWP;
                float v0 = w0*__half2float(pa[i0]) + w1*__half2float(pa[i1])
                         + w2*__half2float(pa[i2]) + w3*__half2float(pa[i3]);
                float v1 = w0*__half2float(pb[i0]) + w1*__half2float(pb[i1])
                         + w2*__half2float(pb[i2]) + w3*__half2float(pb[i3]);
                __half2 h2 = __floats2half2_rn(v0, v1);
                hq[j] = reinterpret_cast<unsigned&>(h2);
            }
            int swo = h ? sw1 : sw0;
            *(uint4*)(vh + swo) = make_uint4(hq[0],hq[1],hq[2],hq[3]);
        }
    };

    fill(0, 0);
    CP_WAIT0();
    __syncthreads();

    // warp tiles: mw in {0,1} (32 px), nw in {0..3} (16 o)
    int mw = wid & 1, nw = wid >> 1;
    int mr = lane & 7, mm = lane >> 3;
    int pixA = mw*32 + (mm & 1)*8 + mr;
    unsigned aRow0 = (unsigned)pixA*128;
    unsigned aRow1 = aRow0 + 16*128;
    unsigned sxa   = (unsigned)((pixA & 7) << 4);
    unsigned hm    = (unsigned)((mm >> 1) * 16);
    int m2 = (lane >> 3) & 1;
    int oR = nw*16 + mr;
    unsigned bRow0 = (unsigned)oR*128;
    unsigned bRow1 = bRow0 + 8*128;
    unsigned sxb   = (unsigned)((oR & 7) << 4);
    unsigned bm    = (unsigned)(m2 * 16);

    float acc[16];
    #pragma unroll
    for (int i = 0; i < 16; ++i) acc[i] = 0.f;

    for (int k = 0; k < 9; ++k) {
        int st = k & 1;
        if (k < 8) {
            int nb = st ^ 1;
            const char* src = (const char*)g_wt + (k+1)*8192;
            cp_async16(sm + SM_WT + nb*8192        + tid*16, src        + tid*16);
            cp_async16(sm + SM_WT + nb*8192 + 4096 + tid*16, src + 4096 + tid*16);
            CP_COMMIT();
            fill(k + 1, nb);
        }

        unsigned vh = smb + SM_VAL + st*8192;
        unsigned wh = smb + SM_WT  + st*8192;

        #pragma unroll
        for (int kc = 0; kc < 4; ++kc) {
            unsigned la = ((unsigned)(kc*32) + hm) ^ sxa;
            unsigned lb = ((unsigned)(kc*32) + bm) ^ sxb;
            unsigned b0a, b0b, b1a, b1b;
            ldsm_x2(b0a, b0b, wh + bRow0 + lb);
            ldsm_x2(b1a, b1b, wh + bRow1 + lb);
            unsigned a0,a1,a2,a3, c0,c1,c2,c3;
            ldsm_x4(a0,a1,a2,a3, vh + aRow0 + la);
            ldsm_x4(c0,c1,c2,c3, vh + aRow1 + la);
            mma16816h(acc+0,  a0,a1,a2,a3, b0a,b0b);
            mma16816h(acc+4,  a0,a1,a2,a3, b1a,b1b);
            mma16816h(acc+8,  c0,c1,c2,c3, b0a,b0b);
            mma16816h(acc+12, c0,c1,c2,c3, b1a,b1b);
        }

        if (k < 8) CP_WAIT0();
        __syncthreads();
    }

    int g  = lane >> 2, tg = lane & 3;
    float* ob = out + (size_t)b*OO*HWP + (size_t)ho*WW + pbase;
    #pragma unroll
    for (int mi = 0; mi < 2; ++mi) {
        #pragma unroll
        for (int ni = 0; ni < 2; ++ni) {
            int p0 = mw*32 + mi*16 + g;
            int o0 = nw*16 + ni*8 + tg*2;
            float bv0 = __ldg(bias + o0), bv1 = __ldg(bias + o0 + 1);
            float* q0 = ob + (size_t)o0*HWP;
            float* q1 = q0 + HWP;
            const float* a = acc + (mi*2 + ni)*4;
            q0[p0]     = a[0] + bv0;
            q1[p0]     = a[1] + bv1;
            q0[p0 + 8] = a[2] + bv0;
            q1[p0 + 8] = a[3] + bv1;
        }
    }
}

extern "C" void kernel_launch(void* const* d_in, const int* in_sizes, int n_in,
                              void* d_out, int out_size)
{
    const float* x    = (const float*)d_in[0];
    const float* ow   = (const float*)d_in[1];
    const float* ob   = (const float*)d_in[2];
    const float* wgt  = (const float*)d_in[3];
    const float* bias = (const float*)d_in[4];
    float* out = (float*)d_out;

    cudaFuncSetAttribute(deform_kernel,
                         cudaFuncAttributeMaxDynamicSharedMemorySize, DEFORM_SMEM);
    cudaFuncSetAttribute(offset_mma_kernel,
                         cudaFuncAttributeMaxDynamicSharedMemorySize, OFFK_SMEM);

    x2h_kernel<<<BB*CC*HWP/1024, 256>>>(x);
    wt_prep_fused<<<(NW1 + NW2 + 255)/256, 256>>>(wgt, ow);
    offset_mma_kernel<<<BB*64, 512, OFFK_SMEM>>>(x, ob);
    deform_kernel<<<BB*HH*2, 256, DEFORM_SMEM>>>(bias, out);
}

// round 17
// speedup vs baseline: 6.1798x; 1.2695x over previous
#include <cuda_runtime.h>
#include <cuda_bf16.h>
#include <cuda_fp16.h>
#include <cstdint>

#define HH 128
#define WW 128
#define HWP (HH*WW)
#define CC 64
#define OO 64
#define BB 4
#define NCH 18

// scratch
__device__ float g_offset[BB*NCH*HH*WW];
__device__ __half g_xh2[BB*HWP*CC];         // NHWC fp16 copy of x (128B per pixel)
// deform weights per tap: 64 o-rows x 128B (64 fp16 ch), XOR-swizzled within row
__device__ __half g_wt[9*4096];
// offset-conv weights per tap: 24 o-rows (18 real + 6 zero) x 128B, swizzled (bf16 hi/lo)
__device__ __nv_bfloat16 g_ow_hi[9*24*64];
__device__ __nv_bfloat16 g_ow_lo[9*24*64];

// ---------------- helpers ----------------
__device__ __forceinline__ void cp_async16(void* smem, const void* gmem) {
    unsigned saddr = (unsigned)__cvta_generic_to_shared(smem);
    asm volatile("cp.async.cg.shared.global [%0], [%1], 16;\n" :: "r"(saddr), "l"(gmem));
}
#define CP_COMMIT() asm volatile("cp.async.commit_group;\n" ::: "memory")
#define CP_WAIT0()  asm volatile("cp.async.wait_group 0;\n" ::: "memory")

__device__ __forceinline__ unsigned su32(const void* p) {
    unsigned a;
    asm("{ .reg .u64 t; cvta.to.shared.u64 t, %1; cvt.u32.u64 %0, t; }" : "=r"(a) : "l"(p));
    return a;
}
__device__ __forceinline__ void ldsm_x4(unsigned& r0, unsigned& r1, unsigned& r2, unsigned& r3, unsigned a) {
    asm volatile("ldmatrix.sync.aligned.m8n8.x4.shared.b16 {%0,%1,%2,%3}, [%4];"
                 : "=r"(r0), "=r"(r1), "=r"(r2), "=r"(r3) : "r"(a));
}
__device__ __forceinline__ void ldsm_x2(unsigned& r0, unsigned& r1, unsigned a) {
    asm volatile("ldmatrix.sync.aligned.m8n8.x2.shared.b16 {%0,%1}, [%2];"
                 : "=r"(r0), "=r"(r1) : "r"(a));
}
// bf16 MMA (offset conv)
__device__ __forceinline__ void mma16816(float* d, unsigned a0, unsigned a1, unsigned a2, unsigned a3,
                                         unsigned b0, unsigned b1) {
    asm volatile(
        "mma.sync.aligned.m16n8k16.row.col.f32.bf16.bf16.f32 "
        "{%0,%1,%2,%3}, {%4,%5,%6,%7}, {%8,%9}, {%0,%1,%2,%3};"
        : "+f"(d[0]), "+f"(d[1]), "+f"(d[2]), "+f"(d[3])
        : "r"(a0), "r"(a1), "r"(a2), "r"(a3), "r"(b0), "r"(b1));
}
// fp16 MMA (deform)
__device__ __forceinline__ void mma16816h(float* d, unsigned a0, unsigned a1, unsigned a2, unsigned a3,
                                          unsigned b0, unsigned b1) {
    asm volatile(
        "mma.sync.aligned.m16n8k16.row.col.f32.f16.f16.f32 "
        "{%0,%1,%2,%3}, {%4,%5,%6,%7}, {%8,%9}, {%0,%1,%2,%3};"
        : "+f"(d[0]), "+f"(d[1]), "+f"(d[2]), "+f"(d[3])
        : "r"(a0), "r"(a1), "r"(a2), "r"(a3), "r"(b0), "r"(b1));
}

// ---------------------------------------------------------------------------
// Kernel 0a: x (NCHW fp32) -> g_xh2 (NHWC fp16). One block per (b,h) row.
// smem tile [w][c] with XOR swizzle; coalesced LDG + coalesced STG.
// ---------------------------------------------------------------------------
__global__ __launch_bounds__(256) void x2nhwc_kernel(const float* __restrict__ x)
{
    __shared__ char tile[128*128];   // 128 px * 128 B
    int tid = threadIdx.x;
    int b   = blockIdx.x >> 7;
    int h   = blockIdx.x & 127;

    for (int i = tid; i < 32*128; i += 256) {
        int c2 = i >> 7, w = i & 127;
        const float* p0 = x + (((size_t)(b*64 + 2*c2)*128 + h)*128 + w);
        float v0 = p0[0];
        float v1 = p0[HWP];
        int byt = (w*128 + c2*4) ^ ((w & 7) << 4);
        *(__half2*)(tile + byt) = __floats2half2_rn(v0, v1);
    }
    __syncthreads();

    uint4* dst = (uint4*)(g_xh2 + (size_t)blockIdx.x * 8192);
    for (int i = tid; i < 1024; i += 256) {
        int px = i >> 3, q = i & 7;
        int byt = (px*128 + q*16) ^ ((px & 7) << 4);
        dst[i] = *(uint4*)(tile + byt);
    }
}

// ---------------------------------------------------------------------------
// Kernel 0b: fused weight prep (deform fp16 + offset bf16 hi/lo)
// ---------------------------------------------------------------------------
#define NW1 (9*4096)
#define NW2 (9*1536)
__global__ void wt_prep_fused(const float* __restrict__ wgt,
                              const float* __restrict__ ow)
{
    int i = blockIdx.x * 256 + threadIdx.x;
    if (i < NW1) {
        int c = i & 63, o = (i >> 6) & 63, k = i >> 12;
        float w = wgt[(o*64 + c)*9 + k];
        int off = (o*128 + c*2) ^ ((o & 7) << 4);
        g_wt[k*4096 + (off >> 1)] = __float2half_rn(w);
    } else if (i < NW1 + NW2) {
        int j = i - NW1;
        int c = j & 63;
        int o = (j >> 6) % 24;
        int k = j / (24*64);
        float w = (o < 18) ? ow[(o*64 + c)*9 + k] : 0.f;
        __nv_bfloat16 hi = __float2bfloat16(w);
        __nv_bfloat16 lo = __float2bfloat16(w - __bfloat162float(hi));
        int off = (o*128 + c*2) ^ ((o & 7) << 4);
        g_ow_hi[k*1536 + (off >> 1)] = hi;
        g_ow_lo[k*1536 + (off >> 1)] = lo;
    }
}

// ---------------------------------------------------------------------------
// Kernel 1: offset conv3x3 via HMMA (bf16, 3-term) — unchanged (proven)
// ---------------------------------------------------------------------------
#define PLANE 16640
#define SMO_A_LO (4*PLANE)
#define SMO_B    (8*PLANE)
#define OFFK_SMEM (133120 + 55296)

__global__ void __launch_bounds__(512, 1) offset_mma_kernel(
    const float* __restrict__ x,
    const float* __restrict__ ob)
{
    extern __shared__ char sm[];
    int tid  = threadIdx.x;
    int wid  = tid >> 5;
    int lane = tid & 31;
    int b    = blockIdx.x >> 6;
    int ho0  = (blockIdx.x & 63) << 1;

    unsigned smb = su32(sm);
    unsigned Ahi = smb, Alo = smb + SMO_A_LO;
    unsigned Bhi = smb + SMO_B, Blo = Bhi + 27648;

    for (int off = tid*16; off < 27648; off += 8192) {
        cp_async16(sm + SMO_B         + off, (const char*)g_ow_hi + off);
        cp_async16(sm + SMO_B + 27648 + off, (const char*)g_ow_lo + off);
    }
    CP_COMMIT();

    const float* xb = x + (size_t)b*CC*HWP;
    for (int i = tid; i < 4*32*128; i += 512) {
        int w  = i & 127;
        int cp = (i >> 7) & 31;
        int j  = i >> 12;
        int row = ho0 - 1 + j;
        float v0 = 0.f, v1 = 0.f;
        if ((unsigned)row < (unsigned)HH) {
            v0 = xb[((size_t)(2*cp)  *HH + row)*WW + w];
            v1 = xb[((size_t)(2*cp+1)*HH + row)*WW + w];
        }
        __nv_bfloat162 h2 = __floats2bfloat162_rn(v0, v1);
        float r0 = v0 - __bfloat162float(__low2bfloat16(h2));
        float r1 = v1 - __bfloat162float(__high2bfloat16(h2));
        __nv_bfloat162 l2 = __floats2bfloat162_rn(r0, r1);
        int wp  = w + 1;
        int col = (4*cp) ^ ((wp & 7) << 4);
        int byt = j*PLANE + wp*128 + col;
        *(__nv_bfloat162*)(sm + byt)            = h2;
        *(__nv_bfloat162*)(sm + SMO_A_LO + byt) = l2;
    }
    for (int i = tid; i < 4*2*32; i += 512) {
        int cp = i & 31, e = (i >> 5) & 1, j = i >> 6;
        int wp = e ? 129 : 0;
        int col = (4*cp) ^ ((wp & 7) << 4);
        int byt = j*PLANE + wp*128 + col;
        *(unsigned*)(sm + byt)            = 0u;
        *(unsigned*)(sm + SMO_A_LO + byt) = 0u;
    }
    CP_WAIT0();
    __syncthreads();

    int r  = wid >> 3;
    int pb = (wid & 7) * 16;
    int mr = lane & 7, mm = lane >> 3;
    int p_frag = pb + (mm & 1)*8 + mr;
    unsigned hm = (unsigned)((mm >> 1) * 16);
    unsigned bm = (unsigned)(((lane >> 3) & 1) * 16);

    float acc[12];
    #pragma unroll
    for (int i = 0; i < 12; ++i) acc[i] = 0.f;

    #pragma unroll
    for (int k = 0; k < 9; ++k) {
        int ky = k / 3, kx = k - 3*ky;
        unsigned aPlaneH = Ahi + (unsigned)((r + ky)*PLANE);
        unsigned aPlaneL = Alo + (unsigned)((r + ky)*PLANE);
        int roww = p_frag + kx;
        unsigned arow = (unsigned)(roww*128);
        unsigned sx   = (unsigned)((roww & 7) << 4);
        unsigned bk   = (unsigned)(k*3072);
        #pragma unroll
        for (int kc = 0; kc < 4; ++kc) {
            unsigned la = ((unsigned)(kc*32) + hm) ^ sx;
            unsigned ah0,ah1,ah2,ah3, al0,al1,al2,al3;
            ldsm_x4(ah0,ah1,ah2,ah3, aPlaneH + arow + la);
            ldsm_x4(al0,al1,al2,al3, aPlaneL + arow + la);
            unsigned lb = ((unsigned)(kc*32) + bm) ^ ((unsigned)(mr << 4));
            #pragma unroll
            for (int nt = 0; nt < 3; ++nt) {
                unsigned brow = bk + (unsigned)(nt*1024 + mr*128);
                unsigned bh0, bh1, bl0, bl1;
                ldsm_x2(bh0, bh1, Bhi + brow + lb);
                ldsm_x2(bl0, bl1, Blo + brow + lb);
                mma16816(acc + nt*4, ah0,ah1,ah2,ah3, bh0,bh1);
                mma16816(acc + nt*4, ah0,ah1,ah2,ah3, bl0,bl1);
                mma16816(acc + nt*4, al0,al1,al2,al3, bh0,bh1);
            }
        }
    }

    int g = lane >> 2, tg = lane & 3;
    int how = ho0 + r;
    #pragma unroll
    for (int nt = 0; nt < 3; ++nt) {
        #pragma unroll
        for (int sub = 0; sub < 2; ++sub) {
            int o = nt*8 + tg*2 + sub;
            if (o < NCH) {
                float bv = __ldg(ob + o);
                float* q = g_offset + (((size_t)b*NCH + o)*HH + how)*WW;
                q[pb + g]     = acc[nt*4 + sub]     + bv;
                q[pb + g + 8] = acc[nt*4 + 2 + sub] + bv;
            }
        }
    }
}

// ---------------------------------------------------------------------------
// Kernel 2: deformable conv — fp16 HMMA, half-row CTAs, NHWC wide gathers.
// Thread map for fill: cb = tid&3 (16-ch chunk), pv = tid>>2 (pixel).
// Per tap per thread: 4 corners x 2 LDG.128 (split into two 8-ch halves),
// fp32 blend, 2 STS.128.
// ---------------------------------------------------------------------------
#define SM_VAL   0        // stage*8192
#define SM_WT    16384    // stage*8192
#define SM_PP    32768    // 9*64*2 floats = 4608 B
#define DEFORM_SMEM (32768 + 4608)

__global__ void __launch_bounds__(256, 4) deform_kernel(
    const float* __restrict__ bias,
    float* __restrict__ out)
{
    extern __shared__ char sm[];
    float* pp_s = (float*)(sm + SM_PP);

    int tid   = threadIdx.x;
    int wid   = tid >> 5;
    int lane  = tid & 31;
    int blk   = blockIdx.x;
    int b     = blk >> 8;
    int ho    = (blk >> 1) & 127;
    int pbase = (blk & 1) << 6;   // 0 or 64

    unsigned smb = su32(sm);

    // stage sampling positions for 9 taps x 64 px
    for (int i = tid; i < 9*64; i += 256) {
        int k = i >> 6, p = i & 63;
        int gp = pbase + p;
        int ky = k / 3, kx = k - ky*3;
        const float* offp = g_offset + (((size_t)b*NCH + 2*k)*HH + ho)*WW + gp;
        pp_s[i*2+0] = (float)(ho - 1 + ky) + offp[0];
        pp_s[i*2+1] = (float)(gp - 1 + kx) + offp[HWP];
    }

    // prefetch wt tap 0 (8KB = 256 threads x 2 x 16B)
    cp_async16(sm + SM_WT        + tid*16, (const char*)g_wt        + tid*16);
    cp_async16(sm + SM_WT + 4096 + tid*16, (const char*)g_wt + 4096 + tid*16);
    CP_COMMIT();

    __syncthreads();   // pp_s visible before fill(0)

    int cb = tid & 3;     // 16-ch chunk
    int pv = tid >> 2;    // pixel within half-row
    const char* xb2 = (const char*)g_xh2 + (size_t)b*HWP*128;
    int cb32 = cb*32;

    int sA = pv*128 + cb32;
    int sw0 = sA        ^ ((pv & 7) << 4);
    int sw1 = (sA + 16) ^ ((pv & 7) << 4);

    auto fill = [&](int k, int st) {
        float py = pp_s[(k*64 + pv)*2 + 0];
        float px = pp_s[(k*64 + pv)*2 + 1];
        float fy0 = floorf(py), fx0 = floorf(px);
        int y0 = (int)fy0, x0 = (int)fx0;
        int y1 = y0 + 1,   x1 = x0 + 1;
        float wy1 = py - fy0, wx1 = px - fx0;
        float wy0 = 1.f - wy1, wx0 = 1.f - wx1;
        float vy0 = ((unsigned)y0 < (unsigned)HH) ? 1.f : 0.f;
        float vy1 = ((unsigned)y1 < (unsigned)HH) ? 1.f : 0.f;
        float vx0 = ((unsigned)x0 < (unsigned)WW) ? 1.f : 0.f;
        float vx1 = ((unsigned)x1 < (unsigned)WW) ? 1.f : 0.f;
        int cy0 = min(max(y0,0),HH-1), cy1 = min(max(y1,0),HH-1);
        int cx0 = min(max(x0,0),WW-1), cx1 = min(max(x1,0),WW-1);
        float w0 = wy0*wx0*vy0*vx0, w1 = wy0*wx1*vy0*vx1,
              w2 = wy1*wx0*vy1*vx0, w3 = wy1*wx1*vy1*vx1;
        int a0 = (cy0*WW + cx0)*128 + cb32;
        int a1 = (cy0*WW + cx1)*128 + cb32;
        int a2 = (cy1*WW + cx0)*128 + cb32;
        int a3 = (cy1*WW + cx1)*128 + cb32;

        char* vh = sm + SM_VAL + st*8192;

        #pragma unroll
        for (int h = 0; h < 2; ++h) {
            int hb = h*16;
            uint4 q0 = *(const uint4*)(xb2 + a0 + hb);
            uint4 q1 = *(const uint4*)(xb2 + a1 + hb);
            uint4 q2 = *(const uint4*)(xb2 + a2 + hb);
            uint4 q3 = *(const uint4*)(xb2 + a3 + hb);
            unsigned r0[4] = {q0.x,q0.y,q0.z,q0.w};
            unsigned r1[4] = {q1.x,q1.y,q1.z,q1.w};
            unsigned r2[4] = {q2.x,q2.y,q2.z,q2.w};
            unsigned r3[4] = {q3.x,q3.y,q3.z,q3.w};
            unsigned hq[4];
            #pragma unroll
            for (int j = 0; j < 4; ++j) {
                float2 f0 = __half22float2(*reinterpret_cast<__half2*>(&r0[j]));
                float2 f1 = __half22float2(*reinterpret_cast<__half2*>(&r1[j]));
                float2 f2 = __half22float2(*reinterpret_cast<__half2*>(&r2[j]));
                float2 f3 = __half22float2(*reinterpret_cast<__half2*>(&r3[j]));
                float ux = w0*f0.x + w1*f1.x + w2*f2.x + w3*f3.x;
                float uy = w0*f0.y + w1*f1.y + w2*f2.y + w3*f3.y;
                __half2 hh = __floats2half2_rn(ux, uy);
                hq[j] = reinterpret_cast<unsigned&>(hh);
            }
            *(uint4*)(vh + (h ? sw1 : sw0)) = make_uint4(hq[0],hq[1],hq[2],hq[3]);
        }
    };

    fill(0, 0);
    CP_WAIT0();
    __syncthreads();

    // warp tiles: mw in {0,1} (32 px), nw in {0..3} (16 o)
    int mw = wid & 1, nw = wid >> 1;
    int mr = lane & 7, mm = lane >> 3;
    int pixA = mw*32 + (mm & 1)*8 + mr;
    unsigned aRow0 = (unsigned)pixA*128;
    unsigned aRow1 = aRow0 + 16*128;
    unsigned sxa   = (unsigned)((pixA & 7) << 4);
    unsigned hm    = (unsigned)((mm >> 1) * 16);
    int m2 = (lane >> 3) & 1;
    int oR = nw*16 + mr;
    unsigned bRow0 = (unsigned)oR*128;
    unsigned bRow1 = bRow0 + 8*128;
    unsigned sxb   = (unsigned)((oR & 7) << 4);
    unsigned bm    = (unsigned)(m2 * 16);

    float acc[16];
    #pragma unroll
    for (int i = 0; i < 16; ++i) acc[i] = 0.f;

    for (int k = 0; k < 9; ++k) {
        int st = k & 1;
        if (k < 8) {
            int nb = st ^ 1;
            const char* src = (const char*)g_wt + (k+1)*8192;
            cp_async16(sm + SM_WT + nb*8192        + tid*16, src        + tid*16);
            cp_async16(sm + SM_WT + nb*8192 + 4096 + tid*16, src + 4096 + tid*16);
            CP_COMMIT();
            fill(k + 1, nb);
        }

        unsigned vh = smb + SM_VAL + st*8192;
        unsigned wh = smb + SM_WT  + st*8192;

        #pragma unroll
        for (int kc = 0; kc < 4; ++kc) {
            unsigned la = ((unsigned)(kc*32) + hm) ^ sxa;
            unsigned lb = ((unsigned)(kc*32) + bm) ^ sxb;
            unsigned b0a, b0b, b1a, b1b;
            ldsm_x2(b0a, b0b, wh + bRow0 + lb);
            ldsm_x2(b1a, b1b, wh + bRow1 + lb);
            unsigned a0,a1,a2,a3, c0,c1,c2,c3;
            ldsm_x4(a0,a1,a2,a3, vh + aRow0 + la);
            ldsm_x4(c0,c1,c2,c3, vh + aRow1 + la);
            mma16816h(acc+0,  a0,a1,a2,a3, b0a,b0b);
            mma16816h(acc+4,  a0,a1,a2,a3, b1a,b1b);
            mma16816h(acc+8,  c0,c1,c2,c3, b0a,b0b);
            mma16816h(acc+12, c0,c1,c2,c3, b1a,b1b);
        }

        if (k < 8) CP_WAIT0();
        __syncthreads();
    }

    int g  = lane >> 2, tg = lane & 3;
    float* ob = out + (size_t)b*OO*HWP + (size_t)ho*WW + pbase;
    #pragma unroll
    for (int mi = 0; mi < 2; ++mi) {
        #pragma unroll
        for (int ni = 0; ni < 2; ++ni) {
            int p0 = mw*32 + mi*16 + g;
            int o0 = nw*16 + ni*8 + tg*2;
            float bv0 = __ldg(bias + o0), bv1 = __ldg(bias + o0 + 1);
            float* q0 = ob + (size_t)o0*HWP;
            float* q1 = q0 + HWP;
            const float* a = acc + (mi*2 + ni)*4;
            q0[p0]     = a[0] + bv0;
            q1[p0]     = a[1] + bv1;
            q0[p0 + 8] = a[2] + bv0;
            q1[p0 + 8] = a[3] + bv1;
        }
    }
}

extern "C" void kernel_launch(void* const* d_in, const int* in_sizes, int n_in,
                              void* d_out, int out_size)
{
    const float* x    = (const float*)d_in[0];
    const float* ow   = (const float*)d_in[1];
    const float* ob   = (const float*)d_in[2];
    const float* wgt  = (const float*)d_in[3];
    const float* bias = (const float*)d_in[4];
    float* out = (float*)d_out;

    cudaFuncSetAttribute(deform_kernel,
                         cudaFuncAttributeMaxDynamicSharedMemorySize, DEFORM_SMEM);
    cudaFuncSetAttribute(offset_mma_kernel,
                         cudaFuncAttributeMaxDynamicSharedMemorySize, OFFK_SMEM);

    x2nhwc_kernel<<<BB*HH, 256>>>(x);
    wt_prep_fused<<<(NW1 + NW2 + 255)/256, 256>>>(wgt, ow);
    offset_mma_kernel<<<BB*64, 512, OFFK_SMEM>>>(x, ob);
    deform_kernel<<<BB*HH*2, 256, DEFORM_SMEM>>>(bias, out);
}